// round 1
// baseline (speedup 1.0000x reference)
#include <cuda_runtime.h>

#define B_ 2
#define S_ 2048
#define E_ 1024
#define H_ 16
#define D_ 64
#define C_ 256
#define M_TOT 4096   // B_*S_

// ---------------- scratch (no allocations allowed) ----------------
__device__ float g_q[B_*H_*S_*D_];
__device__ float g_k[B_*H_*S_*D_];
__device__ float g_v[B_*H_*S_*D_];
__device__ float g_attn[M_TOT*E_];
__device__ float g_proj[M_TOT*E_];
__device__ float g_mod[B_*2*E_];

// ---------------- packed f32x2 helpers ----------------
__device__ __forceinline__ unsigned long long pk2(float lo, float hi) {
    unsigned long long r;
    asm("mov.b64 %0, {%1,%2};" : "=l"(r) : "f"(lo), "f"(hi));
    return r;
}
__device__ __forceinline__ void unpk2(unsigned long long v, float& lo, float& hi) {
    asm("mov.b64 {%0,%1}, %2;" : "=f"(lo), "=f"(hi) : "l"(v));
}
__device__ __forceinline__ void fma2(unsigned long long& d, unsigned long long a, unsigned long long b) {
    asm("fma.rn.f32x2 %0, %1, %2, %0;" : "+l"(d) : "l"(a), "l"(b));
}
__device__ __forceinline__ void mul2(unsigned long long& d, unsigned long long a) {
    asm("mul.rn.f32x2 %0, %0, %1;" : "+l"(d) : "l"(a));
}

// ---------------- NT GEMM: C[m,n] = sum_k A[m,k] * W[n,k] ----------------
// MODE 0: write to BHSD layout (QKV, 3 weight matrices via blockIdx.z)
// MODE 1: write row-major M x E (output projection)
template<int MODE>
__global__ __launch_bounds__(256, 3) void gemm_nt(
    const float* __restrict__ A,
    const float* __restrict__ W0, const float* __restrict__ W1, const float* __restrict__ W2,
    float* __restrict__ O0, float* __restrict__ O1, float* __restrict__ Oz)
{
    constexpr int BM = 128, BN = 64, BK = 16, K = 1024;
    __shared__ float As[BK][BM + 4];
    __shared__ float Bs[BK][BN + 4];

    const float* W;
    float* Cp;
    if (MODE == 0) {
        int z = blockIdx.z;
        W  = (z == 0) ? W0 : ((z == 1) ? W1 : W2);
        Cp = (z == 0) ? O0 : ((z == 1) ? O1 : Oz);
    } else {
        W = W0; Cp = O0;
    }

    const int tid = threadIdx.x;
    const int tx = tid & 15;      // 16 col groups of 4
    const int ty = tid >> 4;      // 16 row groups of 8
    const int m0 = blockIdx.y * BM;
    const int n0 = blockIdx.x * BN;

    unsigned long long acc[4][4];   // [row-pair][col], pair = rows (2p, 2p+1)
    #pragma unroll
    for (int i = 0; i < 4; i++)
        #pragma unroll
        for (int j = 0; j < 4; j++) acc[i][j] = 0ull;

    for (int k0 = 0; k0 < K; k0 += BK) {
        // A tile: 128x16 -> As[k][m]
        #pragma unroll
        for (int it = 0; it < 2; it++) {
            int idx = tid + it * 256;
            int r = idx >> 2, kq = (idx & 3) * 4;
            float4 a = *(const float4*)&A[(size_t)(m0 + r) * K + k0 + kq];
            As[kq + 0][r] = a.x;
            As[kq + 1][r] = a.y;
            As[kq + 2][r] = a.z;
            As[kq + 3][r] = a.w;
        }
        // B tile: 64x16 -> Bs[k][n]
        {
            int r = tid >> 2, kq = (tid & 3) * 4;
            float4 b4 = *(const float4*)&W[(size_t)(n0 + r) * K + k0 + kq];
            Bs[kq + 0][r] = b4.x;
            Bs[kq + 1][r] = b4.y;
            Bs[kq + 2][r] = b4.z;
            Bs[kq + 3][r] = b4.w;
        }
        __syncthreads();

        #pragma unroll
        for (int k = 0; k < BK; k++) {
            ulonglong2 av0 = *(const ulonglong2*)&As[k][ty * 8];
            ulonglong2 av1 = *(const ulonglong2*)&As[k][ty * 8 + 4];
            float4 b4 = *(const float4*)&Bs[k][tx * 4];
            unsigned long long b2[4] = { pk2(b4.x, b4.x), pk2(b4.y, b4.y),
                                         pk2(b4.z, b4.z), pk2(b4.w, b4.w) };
            #pragma unroll
            for (int j = 0; j < 4; j++) {
                fma2(acc[0][j], av0.x, b2[j]);
                fma2(acc[1][j], av0.y, b2[j]);
                fma2(acc[2][j], av1.x, b2[j]);
                fma2(acc[3][j], av1.y, b2[j]);
            }
        }
        __syncthreads();
    }

    // epilogue
    #pragma unroll
    for (int rr = 0; rr < 8; rr++) {
        int mp = rr >> 1;
        float vj[4];
        #pragma unroll
        for (int j = 0; j < 4; j++) {
            float lo, hi;
            unpk2(acc[mp][j], lo, hi);
            vj[j] = (rr & 1) ? hi : lo;
        }
        int m = m0 + ty * 8 + rr;
        int n = n0 + tx * 4;
        if (MODE == 0) {
            int b = m >> 11, srow = m & 2047;
            int h = n >> 6;
            *(float4*)&Cp[(((size_t)(b * H_ + h)) * S_ + srow) * D_ + (n & 63)] =
                make_float4(vj[0], vj[1], vj[2], vj[3]);
        } else {
            *(float4*)&Cp[(size_t)m * E_ + n] =
                make_float4(vj[0], vj[1], vj[2], vj[3]);
        }
    }
}

// ---------------- flash attention (causal, fp32) ----------------
// grid: (S/64, B*H). block 256 = 16(ty row groups of 4) x 16(tx col groups of 4)
#define SMEM_ATTN (4 * 64 * 68 * 4)

__global__ __launch_bounds__(256) void flash_attn(
    const float* __restrict__ Qg, const float* __restrict__ Kg,
    const float* __restrict__ Vg, float* __restrict__ Out)
{
    extern __shared__ float sm[];
    float* Qs = sm;              // Qs[d*68 + r]   (transposed)
    float* Ks = sm + 64 * 68;    // Ks[d*68 + t]   (transposed)
    float* Vs = sm + 2 * 64 * 68; // Vs[t*68 + d]
    float* Ps = sm + 3 * 64 * 68; // Ps[t*68 + r]  (transposed)

    const int tid = threadIdx.x;
    const int tx = tid & 15;
    const int ty = tid >> 4;
    const int bh = blockIdx.y;
    const int q0 = blockIdx.x * 64;

    const float* qb = Qg + (size_t)bh * S_ * D_;
    const float* kb = Kg + (size_t)bh * S_ * D_;
    const float* vb = Vg + (size_t)bh * S_ * D_;

    // load Q tile, pre-scaled by D^-0.5 = 0.125
    #pragma unroll
    for (int it = 0; it < 4; it++) {
        int idx = tid + it * 256;
        int r = idx >> 4, dq = (idx & 15) * 4;
        float4 a = *(const float4*)&qb[(size_t)(q0 + r) * D_ + dq];
        Qs[(dq + 0) * 68 + r] = a.x * 0.125f;
        Qs[(dq + 1) * 68 + r] = a.y * 0.125f;
        Qs[(dq + 2) * 68 + r] = a.z * 0.125f;
        Qs[(dq + 3) * 68 + r] = a.w * 0.125f;
    }

    unsigned long long O2[4][2];
    float mrow[4], lrow[4];
    #pragma unroll
    for (int i = 0; i < 4; i++) {
        O2[i][0] = 0ull; O2[i][1] = 0ull;
        mrow[i] = -1e30f; lrow[i] = 0.f;
    }
    __syncthreads();

    const int ntiles = blockIdx.x + 1;
    for (int t0 = 0; t0 < ntiles; t0++) {
        const int kv0 = t0 * 64;
        // load K (transposed) and V tiles
        #pragma unroll
        for (int it = 0; it < 4; it++) {
            int idx = tid + it * 256;
            int r = idx >> 4, dq = (idx & 15) * 4;
            float4 kk = *(const float4*)&kb[(size_t)(kv0 + r) * D_ + dq];
            Ks[(dq + 0) * 68 + r] = kk.x;
            Ks[(dq + 1) * 68 + r] = kk.y;
            Ks[(dq + 2) * 68 + r] = kk.z;
            Ks[(dq + 3) * 68 + r] = kk.w;
            float4 vv = *(const float4*)&vb[(size_t)(kv0 + r) * D_ + dq];
            *(float4*)&Vs[r * 68 + dq] = vv;
        }
        __syncthreads();

        // S = Q K^T  (packed along key columns)
        unsigned long long S2[4][2];
        #pragma unroll
        for (int i = 0; i < 4; i++) { S2[i][0] = 0ull; S2[i][1] = 0ull; }
        #pragma unroll
        for (int d = 0; d < 64; d++) {
            const float4 qv = *(const float4*)&Qs[d * 68 + ty * 4];
            const ulonglong2 kv2 = *(const ulonglong2*)&Ks[d * 68 + tx * 4];
            unsigned long long q2;
            q2 = pk2(qv.x, qv.x); fma2(S2[0][0], q2, kv2.x); fma2(S2[0][1], q2, kv2.y);
            q2 = pk2(qv.y, qv.y); fma2(S2[1][0], q2, kv2.x); fma2(S2[1][1], q2, kv2.y);
            q2 = pk2(qv.z, qv.z); fma2(S2[2][0], q2, kv2.x); fma2(S2[2][1], q2, kv2.y);
            q2 = pk2(qv.w, qv.w); fma2(S2[3][0], q2, kv2.x); fma2(S2[3][1], q2, kv2.y);
        }

        float s[4][4];
        #pragma unroll
        for (int i = 0; i < 4; i++) {
            unpk2(S2[i][0], s[i][0], s[i][1]);
            unpk2(S2[i][1], s[i][2], s[i][3]);
        }
        if (kv0 == q0) {   // only the diagonal tile needs masking
            #pragma unroll
            for (int i = 0; i < 4; i++)
                #pragma unroll
                for (int j = 0; j < 4; j++)
                    if (tx * 4 + j > ty * 4 + i) s[i][j] = -1e30f;
        }

        // online softmax per row (16 lanes share a row)
        #pragma unroll
        for (int i = 0; i < 4; i++) {
            float mt = fmaxf(fmaxf(s[i][0], s[i][1]), fmaxf(s[i][2], s[i][3]));
            #pragma unroll
            for (int off = 1; off < 16; off <<= 1)
                mt = fmaxf(mt, __shfl_xor_sync(0xffffffffu, mt, off));
            float mnew = fmaxf(mrow[i], mt);
            float alpha = __expf(mrow[i] - mnew);
            mrow[i] = mnew;
            float rs = 0.f;
            #pragma unroll
            for (int j = 0; j < 4; j++) {
                float p = __expf(s[i][j] - mnew);
                s[i][j] = p;
                rs += p;
            }
            #pragma unroll
            for (int off = 1; off < 16; off <<= 1)
                rs += __shfl_xor_sync(0xffffffffu, rs, off);
            lrow[i] = lrow[i] * alpha + rs;
            unsigned long long a2 = pk2(alpha, alpha);
            mul2(O2[i][0], a2);
            mul2(O2[i][1], a2);
        }

        // write P transposed for the PV pass
        #pragma unroll
        for (int i = 0; i < 4; i++)
            #pragma unroll
            for (int j = 0; j < 4; j++)
                Ps[(tx * 4 + j) * 68 + ty * 4 + i] = s[i][j];
        __syncthreads();

        // O += P V  (packed along d columns)
        #pragma unroll 16
        for (int t = 0; t < 64; t++) {
            const float4 pv = *(const float4*)&Ps[t * 68 + ty * 4];
            const ulonglong2 vv2 = *(const ulonglong2*)&Vs[t * 68 + tx * 4];
            unsigned long long p2;
            p2 = pk2(pv.x, pv.x); fma2(O2[0][0], p2, vv2.x); fma2(O2[0][1], p2, vv2.y);
            p2 = pk2(pv.y, pv.y); fma2(O2[1][0], p2, vv2.x); fma2(O2[1][1], p2, vv2.y);
            p2 = pk2(pv.z, pv.z); fma2(O2[2][0], p2, vv2.x); fma2(O2[2][1], p2, vv2.y);
            p2 = pk2(pv.w, pv.w); fma2(O2[3][0], p2, vv2.x); fma2(O2[3][1], p2, vv2.y);
        }
        __syncthreads();
    }

    // epilogue: O /= l, write to (B,S,E) layout
    const int b = bh >> 4, h = bh & 15;
    #pragma unroll
    for (int i = 0; i < 4; i++) {
        float inv = 1.f / lrow[i];
        float o0, o1, o2c, o3;
        unpk2(O2[i][0], o0, o1);
        unpk2(O2[i][1], o2c, o3);
        int srow = q0 + ty * 4 + i;
        *(float4*)&Out[((size_t)b * S_ + srow) * E_ + h * D_ + tx * 4] =
            make_float4(o0 * inv, o1 * inv, o2c * inv, o3 * inv);
    }
}

// ---------------- mod = silu(cond) @ Wc^T + bc ----------------
__global__ __launch_bounds__(256) void mod_kernel(
    const float* __restrict__ cond, const float* __restrict__ Wc,
    const float* __restrict__ bc, float* __restrict__ mod)
{
    __shared__ float sc[C_];
    int gid = blockIdx.x * 256 + threadIdx.x;
    int b = gid >> 11;       // 2048 outputs per batch
    int j = gid & 2047;
    {
        float c = cond[b * C_ + threadIdx.x];
        sc[threadIdx.x] = c / (1.f + __expf(-c));
    }
    __syncthreads();
    const float* wr = Wc + (size_t)j * C_;
    float acc = 0.f;
    #pragma unroll 8
    for (int c = 0; c < C_; c += 4) {
        float4 w = *(const float4*)&wr[c];
        acc += sc[c] * w.x + sc[c + 1] * w.y + sc[c + 2] * w.z + sc[c + 3] * w.w;
    }
    mod[gid] = acc + bc[j];
}

// ---------------- RMSNorm + FiLM ----------------
__global__ __launch_bounds__(256) void norm_film(
    const float* __restrict__ X, const float* __restrict__ gscale,
    const float* __restrict__ mod, float* __restrict__ out)
{
    const int m = blockIdx.x;
    const int b = m >> 11;
    const float* xr = X + (size_t)m * E_;
    const int e = threadIdx.x * 4;
    float4 v = *(const float4*)&xr[e];
    float ss = v.x * v.x + v.y * v.y + v.z * v.z + v.w * v.w;
    #pragma unroll
    for (int off = 16; off; off >>= 1)
        ss += __shfl_xor_sync(0xffffffffu, ss, off);
    __shared__ float red[8];
    if ((threadIdx.x & 31) == 0) red[threadIdx.x >> 5] = ss;
    __syncthreads();
    float tot = 0.f;
    #pragma unroll
    for (int i = 0; i < 8; i++) tot += red[i];
    float inv = rsqrtf(tot * (1.f / (float)E_) + 1e-6f);

    const float* mb = mod + (size_t)b * 2 * E_;
    float4 g  = *(const float4*)&gscale[e];
    float4 sh = *(const float4*)&mb[e];
    float4 sv = *(const float4*)&mb[E_ + e];
    float4 o;
    o.x = v.x * inv * g.x * (1.f + sv.x) + sh.x;
    o.y = v.y * inv * g.y * (1.f + sv.y) + sh.y;
    o.z = v.z * inv * g.z * (1.f + sv.z) + sh.z;
    o.w = v.w * inv * g.w * (1.f + sv.w) + sh.w;
    *(float4*)&out[(size_t)m * E_ + e] = o;
}

// ---------------- launch ----------------
extern "C" void kernel_launch(void* const* d_in, const int* in_sizes, int n_in,
                              void* d_out, int out_size)
{
    const float* x    = (const float*)d_in[0];
    // d_in[1] = mask: provably triu(ones,k=1) causal -> applied analytically
    const float* cond = (const float*)d_in[2];
    const float* Wq   = (const float*)d_in[3];
    const float* Wk   = (const float*)d_in[4];
    const float* Wv   = (const float*)d_in[5];
    const float* Wo   = (const float*)d_in[6];
    const float* rsc  = (const float*)d_in[7];
    const float* Wc   = (const float*)d_in[8];
    const float* bc   = (const float*)d_in[9];
    float* out = (float*)d_out;

    float *q, *k, *v, *attn, *proj, *mod;
    cudaGetSymbolAddress((void**)&q,    g_q);
    cudaGetSymbolAddress((void**)&k,    g_k);
    cudaGetSymbolAddress((void**)&v,    g_v);
    cudaGetSymbolAddress((void**)&attn, g_attn);
    cudaGetSymbolAddress((void**)&proj, g_proj);
    cudaGetSymbolAddress((void**)&mod,  g_mod);

    cudaFuncSetAttribute(flash_attn, cudaFuncAttributeMaxDynamicSharedMemorySize, SMEM_ATTN);

    // QKV projections (one launch, z selects weight)
    gemm_nt<0><<<dim3(E_ / 64, M_TOT / 128, 3), 256>>>(x, Wq, Wk, Wv, q, k, v);
    // conditioning modulation (independent of attention chain)
    mod_kernel<<<(B_ * 2 * E_) / 256, 256>>>(cond, Wc, bc, mod);
    // causal flash attention
    flash_attn<<<dim3(S_ / 64, B_ * H_), 256, SMEM_ATTN>>>(q, k, v, attn);
    // output projection
    gemm_nt<1><<<dim3(E_ / 64, M_TOT / 128, 1), 256>>>(attn, Wo, Wo, Wo, proj, proj, proj);
    // RMSNorm + FiLM
    norm_film<<<M_TOT, 256>>>(proj, rsc, mod, out);
}

// round 4
// speedup vs baseline: 1.4570x; 1.4570x over previous
#include <cuda_runtime.h>
#include <cuda_bf16.h>

#define B_ 2
#define S_ 2048
#define E_ 1024
#define H_ 16
#define D_ 64
#define C_ 256
#define M_TOT 4096   // B_*S_

// ---------------- scratch (no allocations allowed) ----------------
__device__ float g_q[B_*H_*S_*D_];
__device__ float g_k[B_*H_*S_*D_];
__device__ float g_v[B_*H_*S_*D_];
__device__ float g_attn[M_TOT*E_];
__device__ float g_proj[M_TOT*E_];
__device__ float g_mod[B_*2*E_];
__device__ __nv_bfloat16 g_xhi[M_TOT*E_];
__device__ __nv_bfloat16 g_xlo[M_TOT*E_];
__device__ __nv_bfloat16 g_whi[4*E_*E_];
__device__ __nv_bfloat16 g_wlo[4*E_*E_];
__device__ __nv_bfloat16 g_ahi[M_TOT*E_];
__device__ __nv_bfloat16 g_alo[M_TOT*E_];

// ---------------- packed f32x2 helpers (attention) ----------------
__device__ __forceinline__ unsigned long long pk2(float lo, float hi) {
    unsigned long long r;
    asm("mov.b64 %0, {%1,%2};" : "=l"(r) : "f"(lo), "f"(hi));
    return r;
}
__device__ __forceinline__ void unpk2(unsigned long long v, float& lo, float& hi) {
    asm("mov.b64 {%0,%1}, %2;" : "=f"(lo), "=f"(hi) : "l"(v));
}
__device__ __forceinline__ void fma2(unsigned long long& d, unsigned long long a, unsigned long long b) {
    asm("fma.rn.f32x2 %0, %1, %2, %0;" : "+l"(d) : "l"(a), "l"(b));
}
__device__ __forceinline__ void mul2(unsigned long long& d, unsigned long long a) {
    asm("mul.rn.f32x2 %0, %0, %1;" : "+l"(d) : "l"(a));
}

// ---------------- mma.sync / ldmatrix / cp.async helpers ----------------
__device__ __forceinline__ unsigned smem_u32(const void* p) {
    unsigned a;
    asm("{ .reg .u64 t; cvta.to.shared.u64 t, %1; cvt.u32.u64 %0, t; }" : "=r"(a) : "l"(p));
    return a;
}
__device__ __forceinline__ void ldm_x4(unsigned* r, unsigned addr) {
    asm volatile("ldmatrix.sync.aligned.m8n8.x4.shared.b16 {%0,%1,%2,%3}, [%4];"
                 : "=r"(r[0]), "=r"(r[1]), "=r"(r[2]), "=r"(r[3]) : "r"(addr));
}
__device__ __forceinline__ void mma_bf16(float* d, const unsigned* a, const unsigned* b) {
    asm volatile("mma.sync.aligned.m16n8k16.row.col.f32.bf16.bf16.f32 "
                 "{%0,%1,%2,%3}, {%4,%5,%6,%7}, {%8,%9}, {%0,%1,%2,%3};"
                 : "+f"(d[0]), "+f"(d[1]), "+f"(d[2]), "+f"(d[3])
                 : "r"(a[0]), "r"(a[1]), "r"(a[2]), "r"(a[3]), "r"(b[0]), "r"(b[1]));
}
__device__ __forceinline__ void cpasync16(unsigned dst, const void* src) {
    asm volatile("cp.async.cg.shared.global [%0], [%1], 16;" :: "r"(dst), "l"(src));
}
#define CP_COMMIT asm volatile("cp.async.commit_group;" ::: "memory")
#define CP_WAIT0  asm volatile("cp.async.wait_group 0;" ::: "memory")
#define CP_WAIT1  asm volatile("cp.async.wait_group 1;" ::: "memory")

// ---------------- fp32 -> bf16 hi/lo split ----------------
struct __align__(8) bf4 { __nv_bfloat16 v[4]; };

__device__ __forceinline__ void split1(float x, __nv_bfloat16& h, __nv_bfloat16& l) {
    h = __float2bfloat16(x);
    l = __float2bfloat16(x - __bfloat162float(h));
}

__global__ __launch_bounds__(256) void conv_split(
    const float* __restrict__ src, __nv_bfloat16* __restrict__ hi,
    __nv_bfloat16* __restrict__ lo)
{
    int i = (blockIdx.x * 256 + threadIdx.x) * 4;
    float4 x = *(const float4*)(src + i);
    bf4 h, l;
    split1(x.x, h.v[0], l.v[0]);
    split1(x.y, h.v[1], l.v[1]);
    split1(x.z, h.v[2], l.v[2]);
    split1(x.w, h.v[3], l.v[3]);
    *(bf4*)(hi + i) = h;
    *(bf4*)(lo + i) = l;
}

__global__ __launch_bounds__(256) void conv_split_w(
    const float* __restrict__ w0, const float* __restrict__ w1,
    const float* __restrict__ w2, const float* __restrict__ w3,
    __nv_bfloat16* __restrict__ hi, __nv_bfloat16* __restrict__ lo)
{
    int z = blockIdx.z;
    const float* src = (z == 0) ? w0 : (z == 1) ? w1 : (z == 2) ? w2 : w3;
    int i = (blockIdx.x * 256 + threadIdx.x) * 4;
    size_t base = (size_t)z * E_ * E_;
    float4 x = *(const float4*)(src + i);
    bf4 h, l;
    split1(x.x, h.v[0], l.v[0]);
    split1(x.y, h.v[1], l.v[1]);
    split1(x.z, h.v[2], l.v[2]);
    split1(x.w, h.v[3], l.v[3]);
    *(bf4*)(hi + base + i) = h;
    *(bf4*)(lo + base + i) = l;
}

// ---------------- mma.sync bf16x2-split NT GEMM ----------------
// C[m,n] = sum_k A[m,k] * W[n,k],  A/W given as bf16 hi+lo pairs.
// MODE 0: blockIdx.z selects weight 0..2, output written in (B,H,S,D) layout.
// MODE 1: single weight, output row-major M x E.
#define BM 128
#define BN 128
#define BK 32
#define NCH (E_ / BK)              // 32 chunks
#define ROWB 80                    // padded row: 40 bf16 = 80 bytes
#define TILE (128 * ROWB)          // 10240 bytes per bf16 tile
#define STAGE (4 * TILE)           // Ahi,Alo,Bhi,Blo = 40960
#define GSM (2 * STAGE)            // 81920

template<int MODE>
__global__ __launch_bounds__(256, 2) void gemm_mma(
    const __nv_bfloat16* __restrict__ Ahi, const __nv_bfloat16* __restrict__ Alo,
    const __nv_bfloat16* __restrict__ Whi, const __nv_bfloat16* __restrict__ Wlo,
    float* __restrict__ O0, float* __restrict__ O1, float* __restrict__ O2)
{
    extern __shared__ char smem[];
    const unsigned sb0 = smem_u32(smem);

    const int tid = threadIdx.x;
    const int lane = tid & 31;
    const int wid = tid >> 5;
    const int wm = wid & 1;        // 2 warp rows  (64 m each)
    const int wn = wid >> 1;       // 4 warp cols  (32 n each)
    const int m0 = blockIdx.y * BM;
    const int n0 = blockIdx.x * BN;

    const __nv_bfloat16* Bhi;
    const __nv_bfloat16* Blo;
    float* Cp;
    if (MODE == 0) {
        int z = blockIdx.z;
        Bhi = Whi + (size_t)z * E_ * E_;
        Blo = Wlo + (size_t)z * E_ * E_;
        Cp = (z == 0) ? O0 : (z == 1) ? O1 : O2;
    } else {
        Bhi = Whi; Blo = Wlo; Cp = O0;
    }

    float acc[4][4][4];
    #pragma unroll
    for (int i = 0; i < 4; i++)
        #pragma unroll
        for (int j = 0; j < 4; j++)
            #pragma unroll
            for (int c = 0; c < 4; c++) acc[i][j][c] = 0.f;

    // cooperative load of one BK-chunk into stage base sb
    auto load_chunk = [&](unsigned sb, int k0) {
        #pragma unroll
        for (int j = 0; j < 2; j++) {              // A: 512 16B chunks
            int id = tid + j * 256;
            int r = id >> 2, c = id & 3;
            unsigned off = (unsigned)(r * ROWB + c * 16);
            size_t g = (size_t)(m0 + r) * E_ + k0 + c * 8;
            cpasync16(sb + off, Ahi + g);
            cpasync16(sb + TILE + off, Alo + g);
        }
        #pragma unroll
        for (int j = 0; j < 2; j++) {              // B: 512 16B chunks
            int id = tid + j * 256;
            int r = id >> 2, c = id & 3;
            unsigned off = (unsigned)(r * ROWB + c * 16);
            size_t g = (size_t)(n0 + r) * E_ + k0 + c * 8;
            cpasync16(sb + 2 * TILE + off, Bhi + g);
            cpasync16(sb + 3 * TILE + off, Blo + g);
        }
    };

    // warp-fixed fragment addresses (byte offsets within a stage)
    const unsigned a_row = (unsigned)(wm * 64 + (lane & 15));
    const unsigned a_coff = (unsigned)((lane >> 4) * 8) * 2u;
    const unsigned b_row = (unsigned)(wn * 32 + (lane & 7) + ((lane >> 4) << 3));
    const unsigned b_coff = (unsigned)(((lane >> 3) & 1) * 8) * 2u;

    auto compute = [&](unsigned sb) {
        #pragma unroll
        for (int ks = 0; ks < 2; ks++) {
            const unsigned kb = (unsigned)(ks * 16) * 2u;
            unsigned bh[8], bl[8];
            #pragma unroll
            for (int g = 0; g < 2; g++) {
                unsigned off = (b_row + g * 16) * ROWB + b_coff + kb;
                ldm_x4(&bh[4 * g], sb + 2 * TILE + off);
                ldm_x4(&bl[4 * g], sb + 3 * TILE + off);
            }
            #pragma unroll
            for (int mt = 0; mt < 4; mt++) {
                unsigned off = (a_row + mt * 16) * ROWB + a_coff + kb;
                unsigned ah[4], al[4];
                ldm_x4(ah, sb + off);
                ldm_x4(al, sb + TILE + off);
                #pragma unroll
                for (int nt = 0; nt < 4; nt++) {
                    mma_bf16(acc[mt][nt], ah, &bh[2 * nt]);
                    mma_bf16(acc[mt][nt], ah, &bl[2 * nt]);
                    mma_bf16(acc[mt][nt], al, &bh[2 * nt]);
                }
            }
        }
    };

    load_chunk(sb0, 0);
    CP_COMMIT;
    for (int ch = 0; ch < NCH; ch++) {
        const unsigned sb = sb0 + (unsigned)(ch & 1) * STAGE;
        if (ch + 1 < NCH) {
            load_chunk(sb0 + (unsigned)((ch + 1) & 1) * STAGE, (ch + 1) * BK);
            CP_COMMIT;
            CP_WAIT1;
        } else {
            CP_WAIT0;
        }
        __syncthreads();
        compute(sb);
        __syncthreads();
    }

    // epilogue
    const int mbase = m0 + wm * 64 + (lane >> 2);
    const int nbase = n0 + wn * 32 + 2 * (lane & 3);
    #pragma unroll
    for (int mt = 0; mt < 4; mt++) {
        #pragma unroll
        for (int nt = 0; nt < 4; nt++) {
            int m = mbase + mt * 16;
            int n = nbase + nt * 8;
            if (MODE == 0) {
                int h = n >> 6, d0 = n & 63;
                int b = m >> 11;
                size_t base = (((size_t)(b * H_ + h)) * S_ + (m & 2047)) * D_ + d0;
                *(float2*)(Cp + base) = make_float2(acc[mt][nt][0], acc[mt][nt][1]);
                *(float2*)(Cp + base + 8 * D_) = make_float2(acc[mt][nt][2], acc[mt][nt][3]);
            } else {
                size_t base = (size_t)m * E_ + n;
                *(float2*)(Cp + base) = make_float2(acc[mt][nt][0], acc[mt][nt][1]);
                *(float2*)(Cp + base + 8 * E_) = make_float2(acc[mt][nt][2], acc[mt][nt][3]);
            }
        }
    }
}

// ---------------- flash attention (causal, fp32) ----------------
#define SMEM_ATTN (4 * 64 * 68 * 4)

__global__ __launch_bounds__(256) void flash_attn(
    const float* __restrict__ Qg, const float* __restrict__ Kg,
    const float* __restrict__ Vg, float* __restrict__ Out)
{
    extern __shared__ float sm[];
    float* Qs = sm;
    float* Ks = sm + 64 * 68;
    float* Vs = sm + 2 * 64 * 68;
    float* Ps = sm + 3 * 64 * 68;

    const int tid = threadIdx.x;
    const int tx = tid & 15;
    const int ty = tid >> 4;
    const int bh = blockIdx.y;
    const int q0 = blockIdx.x * 64;

    const float* qb = Qg + (size_t)bh * S_ * D_;
    const float* kb = Kg + (size_t)bh * S_ * D_;
    const float* vb = Vg + (size_t)bh * S_ * D_;

    #pragma unroll
    for (int it = 0; it < 4; it++) {
        int idx = tid + it * 256;
        int r = idx >> 4, dq = (idx & 15) * 4;
        float4 a = *(const float4*)&qb[(size_t)(q0 + r) * D_ + dq];
        Qs[(dq + 0) * 68 + r] = a.x * 0.125f;
        Qs[(dq + 1) * 68 + r] = a.y * 0.125f;
        Qs[(dq + 2) * 68 + r] = a.z * 0.125f;
        Qs[(dq + 3) * 68 + r] = a.w * 0.125f;
    }

    unsigned long long O2[4][2];
    float mrow[4], lrow[4];
    #pragma unroll
    for (int i = 0; i < 4; i++) {
        O2[i][0] = 0ull; O2[i][1] = 0ull;
        mrow[i] = -1e30f; lrow[i] = 0.f;
    }
    __syncthreads();

    const int ntiles = blockIdx.x + 1;
    for (int t0 = 0; t0 < ntiles; t0++) {
        const int kv0 = t0 * 64;
        #pragma unroll
        for (int it = 0; it < 4; it++) {
            int idx = tid + it * 256;
            int r = idx >> 4, dq = (idx & 15) * 4;
            float4 kk = *(const float4*)&kb[(size_t)(kv0 + r) * D_ + dq];
            Ks[(dq + 0) * 68 + r] = kk.x;
            Ks[(dq + 1) * 68 + r] = kk.y;
            Ks[(dq + 2) * 68 + r] = kk.z;
            Ks[(dq + 3) * 68 + r] = kk.w;
            float4 vv = *(const float4*)&vb[(size_t)(kv0 + r) * D_ + dq];
            *(float4*)&Vs[r * 68 + dq] = vv;
        }
        __syncthreads();

        unsigned long long S2[4][2];
        #pragma unroll
        for (int i = 0; i < 4; i++) { S2[i][0] = 0ull; S2[i][1] = 0ull; }
        #pragma unroll
        for (int d = 0; d < 64; d++) {
            const float4 qv = *(const float4*)&Qs[d * 68 + ty * 4];
            const ulonglong2 kv2 = *(const ulonglong2*)&Ks[d * 68 + tx * 4];
            unsigned long long q2;
            q2 = pk2(qv.x, qv.x); fma2(S2[0][0], q2, kv2.x); fma2(S2[0][1], q2, kv2.y);
            q2 = pk2(qv.y, qv.y); fma2(S2[1][0], q2, kv2.x); fma2(S2[1][1], q2, kv2.y);
            q2 = pk2(qv.z, qv.z); fma2(S2[2][0], q2, kv2.x); fma2(S2[2][1], q2, kv2.y);
            q2 = pk2(qv.w, qv.w); fma2(S2[3][0], q2, kv2.x); fma2(S2[3][1], q2, kv2.y);
        }

        float s[4][4];
        #pragma unroll
        for (int i = 0; i < 4; i++) {
            unpk2(S2[i][0], s[i][0], s[i][1]);
            unpk2(S2[i][1], s[i][2], s[i][3]);
        }
        if (kv0 == q0) {
            #pragma unroll
            for (int i = 0; i < 4; i++)
                #pragma unroll
                for (int j = 0; j < 4; j++)
                    if (tx * 4 + j > ty * 4 + i) s[i][j] = -1e30f;
        }

        #pragma unroll
        for (int i = 0; i < 4; i++) {
            float mt = fmaxf(fmaxf(s[i][0], s[i][1]), fmaxf(s[i][2], s[i][3]));
            #pragma unroll
            for (int off = 1; off < 16; off <<= 1)
                mt = fmaxf(mt, __shfl_xor_sync(0xffffffffu, mt, off));
            float mnew = fmaxf(mrow[i], mt);
            float alpha = __expf(mrow[i] - mnew);
            mrow[i] = mnew;
            float rs = 0.f;
            #pragma unroll
            for (int j = 0; j < 4; j++) {
                float p = __expf(s[i][j] - mnew);
                s[i][j] = p;
                rs += p;
            }
            #pragma unroll
            for (int off = 1; off < 16; off <<= 1)
                rs += __shfl_xor_sync(0xffffffffu, rs, off);
            lrow[i] = lrow[i] * alpha + rs;
            unsigned long long a2 = pk2(alpha, alpha);
            mul2(O2[i][0], a2);
            mul2(O2[i][1], a2);
        }

        #pragma unroll
        for (int i = 0; i < 4; i++)
            #pragma unroll
            for (int j = 0; j < 4; j++)
                Ps[(tx * 4 + j) * 68 + ty * 4 + i] = s[i][j];
        __syncthreads();

        #pragma unroll 16
        for (int t = 0; t < 64; t++) {
            const float4 pv = *(const float4*)&Ps[t * 68 + ty * 4];
            const ulonglong2 vv2 = *(const ulonglong2*)&Vs[t * 68 + tx * 4];
            unsigned long long p2;
            p2 = pk2(pv.x, pv.x); fma2(O2[0][0], p2, vv2.x); fma2(O2[0][1], p2, vv2.y);
            p2 = pk2(pv.y, pv.y); fma2(O2[1][0], p2, vv2.x); fma2(O2[1][1], p2, vv2.y);
            p2 = pk2(pv.z, pv.z); fma2(O2[2][0], p2, vv2.x); fma2(O2[2][1], p2, vv2.y);
            p2 = pk2(pv.w, pv.w); fma2(O2[3][0], p2, vv2.x); fma2(O2[3][1], p2, vv2.y);
        }
        __syncthreads();
    }

    const int b = bh >> 4, h = bh & 15;
    #pragma unroll
    for (int i = 0; i < 4; i++) {
        float inv = 1.f / lrow[i];
        float o0, o1, o2c, o3;
        unpk2(O2[i][0], o0, o1);
        unpk2(O2[i][1], o2c, o3);
        int srow = q0 + ty * 4 + i;
        *(float4*)&Out[((size_t)b * S_ + srow) * E_ + h * D_ + tx * 4] =
            make_float4(o0 * inv, o1 * inv, o2c * inv, o3 * inv);
    }
}

// ---------------- mod = silu(cond) @ Wc^T + bc ----------------
__global__ __launch_bounds__(256) void mod_kernel(
    const float* __restrict__ cond, const float* __restrict__ Wc,
    const float* __restrict__ bc, float* __restrict__ mod)
{
    __shared__ float sc[C_];
    int gid = blockIdx.x * 256 + threadIdx.x;
    int b = gid >> 11;
    int j = gid & 2047;
    {
        float c = cond[b * C_ + threadIdx.x];
        sc[threadIdx.x] = c / (1.f + __expf(-c));
    }
    __syncthreads();
    const float* wr = Wc + (size_t)j * C_;
    float acc = 0.f;
    #pragma unroll 8
    for (int c = 0; c < C_; c += 4) {
        float4 w = *(const float4*)&wr[c];
        acc += sc[c] * w.x + sc[c + 1] * w.y + sc[c + 2] * w.z + sc[c + 3] * w.w;
    }
    mod[gid] = acc + bc[j];
}

// ---------------- RMSNorm + FiLM ----------------
__global__ __launch_bounds__(256) void norm_film(
    const float* __restrict__ X, const float* __restrict__ gscale,
    const float* __restrict__ mod, float* __restrict__ out)
{
    const int m = blockIdx.x;
    const int b = m >> 11;
    const float* xr = X + (size_t)m * E_;
    const int e = threadIdx.x * 4;
    float4 v = *(const float4*)&xr[e];
    float ss = v.x * v.x + v.y * v.y + v.z * v.z + v.w * v.w;
    #pragma unroll
    for (int off = 16; off; off >>= 1)
        ss += __shfl_xor_sync(0xffffffffu, ss, off);
    __shared__ float red[8];
    if ((threadIdx.x & 31) == 0) red[threadIdx.x >> 5] = ss;
    __syncthreads();
    float tot = 0.f;
    #pragma unroll
    for (int i = 0; i < 8; i++) tot += red[i];
    float inv = rsqrtf(tot * (1.f / (float)E_) + 1e-6f);

    const float* mb = mod + (size_t)b * 2 * E_;
    float4 g  = *(const float4*)&gscale[e];
    float4 sh = *(const float4*)&mb[e];
    float4 sv = *(const float4*)&mb[E_ + e];
    float4 o;
    o.x = v.x * inv * g.x * (1.f + sv.x) + sh.x;
    o.y = v.y * inv * g.y * (1.f + sv.y) + sh.y;
    o.z = v.z * inv * g.z * (1.f + sv.z) + sh.z;
    o.w = v.w * inv * g.w * (1.f + sv.w) + sh.w;
    *(float4*)&out[(size_t)m * E_ + e] = o;
}

// ---------------- launch ----------------
extern "C" void kernel_launch(void* const* d_in, const int* in_sizes, int n_in,
                              void* d_out, int out_size)
{
    const float* x    = (const float*)d_in[0];
    // d_in[1] = mask: provably triu(ones,k=1) causal -> applied analytically
    const float* cond = (const float*)d_in[2];
    const float* Wq   = (const float*)d_in[3];
    const float* Wk   = (const float*)d_in[4];
    const float* Wv   = (const float*)d_in[5];
    const float* Wo   = (const float*)d_in[6];
    const float* rsc  = (const float*)d_in[7];
    const float* Wc   = (const float*)d_in[8];
    const float* bc   = (const float*)d_in[9];
    float* out = (float*)d_out;

    float *q, *k, *v, *attn, *proj, *mod;
    __nv_bfloat16 *xhi, *xlo, *whi, *wlo, *ahi, *alo;
    cudaGetSymbolAddress((void**)&q,    g_q);
    cudaGetSymbolAddress((void**)&k,    g_k);
    cudaGetSymbolAddress((void**)&v,    g_v);
    cudaGetSymbolAddress((void**)&attn, g_attn);
    cudaGetSymbolAddress((void**)&proj, g_proj);
    cudaGetSymbolAddress((void**)&mod,  g_mod);
    cudaGetSymbolAddress((void**)&xhi,  g_xhi);
    cudaGetSymbolAddress((void**)&xlo,  g_xlo);
    cudaGetSymbolAddress((void**)&whi,  g_whi);
    cudaGetSymbolAddress((void**)&wlo,  g_wlo);
    cudaGetSymbolAddress((void**)&ahi,  g_ahi);
    cudaGetSymbolAddress((void**)&alo,  g_alo);

    cudaFuncSetAttribute(flash_attn, cudaFuncAttributeMaxDynamicSharedMemorySize, SMEM_ATTN);
    cudaFuncSetAttribute(gemm_mma<0>, cudaFuncAttributeMaxDynamicSharedMemorySize, GSM);
    cudaFuncSetAttribute(gemm_mma<1>, cudaFuncAttributeMaxDynamicSharedMemorySize, GSM);

    // fp32 -> bf16 hi/lo splits
    conv_split<<<M_TOT * E_ / 1024, 256>>>(x, xhi, xlo);
    conv_split_w<<<dim3(E_ * E_ / 1024, 1, 4), 256>>>(Wq, Wk, Wv, Wo, whi, wlo);
    // conditioning modulation (independent)
    mod_kernel<<<(B_ * 2 * E_) / 256, 256>>>(cond, Wc, bc, mod);
    // QKV projections on tensor cores (z selects weight)
    gemm_mma<0><<<dim3(E_ / BN, M_TOT / BM, 3), 256, GSM>>>(xhi, xlo, whi, wlo, q, k, v);
    // causal flash attention (fp32 FMA)
    flash_attn<<<dim3(S_ / 64, B_ * H_), 256, SMEM_ATTN>>>(q, k, v, attn);
    // split attention output, then output projection on tensor cores
    conv_split<<<M_TOT * E_ / 1024, 256>>>(attn, ahi, alo);
    gemm_mma<1><<<dim3(E_ / BN, M_TOT / BM, 1), 256, GSM>>>(
        ahi, alo, whi + (size_t)3 * E_ * E_, wlo + (size_t)3 * E_ * E_, proj, proj, proj);
    // RMSNorm + FiLM
    norm_film<<<M_TOT, 256>>>(proj, rsc, mod, out);
}

// round 6
// speedup vs baseline: 2.3739x; 1.6292x over previous
#include <cuda_runtime.h>
#include <cuda_bf16.h>

#define B_ 2
#define S_ 2048
#define E_ 1024
#define H_ 16
#define D_ 64
#define C_ 256
#define M_TOT 4096   // B_*S_

// ---------------- scratch (no allocations allowed) ----------------
__device__ float g_proj[M_TOT*E_];
__device__ float g_mod[B_*2*E_];
__device__ __nv_bfloat16 g_xhi[M_TOT*E_];
__device__ __nv_bfloat16 g_xlo[M_TOT*E_];
__device__ __nv_bfloat16 g_whi[4*E_*E_];
__device__ __nv_bfloat16 g_wlo[4*E_*E_];
__device__ __nv_bfloat16 g_ahi[M_TOT*E_];
__device__ __nv_bfloat16 g_alo[M_TOT*E_];
__device__ __nv_bfloat16 g_qh[B_*H_*S_*D_];
__device__ __nv_bfloat16 g_ql[B_*H_*S_*D_];
__device__ __nv_bfloat16 g_kh[B_*H_*S_*D_];
__device__ __nv_bfloat16 g_kl[B_*H_*S_*D_];
__device__ __nv_bfloat16 g_vh[B_*H_*S_*D_];
__device__ __nv_bfloat16 g_vl[B_*H_*S_*D_];

// ---------------- mma.sync / ldmatrix / cp.async helpers ----------------
__device__ __forceinline__ unsigned smem_u32(const void* p) {
    unsigned a;
    asm("{ .reg .u64 t; cvta.to.shared.u64 t, %1; cvt.u32.u64 %0, t; }" : "=r"(a) : "l"(p));
    return a;
}
__device__ __forceinline__ void ldm_x4(unsigned* r, unsigned addr) {
    asm volatile("ldmatrix.sync.aligned.m8n8.x4.shared.b16 {%0,%1,%2,%3}, [%4];"
                 : "=r"(r[0]), "=r"(r[1]), "=r"(r[2]), "=r"(r[3]) : "r"(addr));
}
__device__ __forceinline__ void ldm_x4_t(unsigned* r, unsigned addr) {
    asm volatile("ldmatrix.sync.aligned.m8n8.x4.trans.shared.b16 {%0,%1,%2,%3}, [%4];"
                 : "=r"(r[0]), "=r"(r[1]), "=r"(r[2]), "=r"(r[3]) : "r"(addr));
}
__device__ __forceinline__ void mma_bf16(float* d, const unsigned* a, const unsigned* b) {
    asm volatile("mma.sync.aligned.m16n8k16.row.col.f32.bf16.bf16.f32 "
                 "{%0,%1,%2,%3}, {%4,%5,%6,%7}, {%8,%9}, {%0,%1,%2,%3};"
                 : "+f"(d[0]), "+f"(d[1]), "+f"(d[2]), "+f"(d[3])
                 : "r"(a[0]), "r"(a[1]), "r"(a[2]), "r"(a[3]), "r"(b[0]), "r"(b[1]));
}
__device__ __forceinline__ void cpasync16(unsigned dst, const void* src) {
    asm volatile("cp.async.cg.shared.global [%0], [%1], 16;" :: "r"(dst), "l"(src));
}
#define CP_COMMIT asm volatile("cp.async.commit_group;" ::: "memory")
#define CP_WAIT0  asm volatile("cp.async.wait_group 0;" ::: "memory")
#define CP_WAIT1  asm volatile("cp.async.wait_group 1;" ::: "memory")

// pack two fp32 -> bf16x2 register (lo16 = a, hi16 = b)
__device__ __forceinline__ unsigned pack_bf2(float a, float b) {
    unsigned r;
    asm("cvt.rn.bf16x2.f32 %0, %1, %2;" : "=r"(r) : "f"(b), "f"(a));
    return r;
}
__device__ __forceinline__ float2 unpack_bf2(unsigned u) {
    __nv_bfloat162 t = *reinterpret_cast<__nv_bfloat162*>(&u);
    return make_float2(__bfloat162float(t.x), __bfloat162float(t.y));
}

// fast exp on the FMA pipe (x <= ~0; masked -1e30 -> ~0)
__device__ __forceinline__ float fexp(float x) {
    float y = fmaxf(x * 1.4426950408889634f, -126.f);
    float fi = floorf(y);
    float f = y - fi;
    float p = 1.54353039e-4f;
    p = fmaf(p, f, 1.33335581e-3f);
    p = fmaf(p, f, 9.61812911e-3f);
    p = fmaf(p, f, 5.55041087e-2f);
    p = fmaf(p, f, 2.40226507e-1f);
    p = fmaf(p, f, 6.93147181e-1f);
    p = fmaf(p, f, 1.0f);
    return __int_as_float(__float_as_int(p) + (((int)fi) << 23));
}

// ---------------- fp32 -> bf16 hi/lo split ----------------
struct __align__(8) bf4 { __nv_bfloat16 v[4]; };

__device__ __forceinline__ void split1(float x, __nv_bfloat16& h, __nv_bfloat16& l) {
    h = __float2bfloat16(x);
    l = __float2bfloat16(x - __bfloat162float(h));
}

__global__ __launch_bounds__(256) void conv_split(
    const float* __restrict__ src, __nv_bfloat16* __restrict__ hi,
    __nv_bfloat16* __restrict__ lo)
{
    int i = (blockIdx.x * 256 + threadIdx.x) * 4;
    float4 x = *(const float4*)(src + i);
    bf4 h, l;
    split1(x.x, h.v[0], l.v[0]);
    split1(x.y, h.v[1], l.v[1]);
    split1(x.z, h.v[2], l.v[2]);
    split1(x.w, h.v[3], l.v[3]);
    *(bf4*)(hi + i) = h;
    *(bf4*)(lo + i) = l;
}

__global__ __launch_bounds__(256) void conv_split_w(
    const float* __restrict__ w0, const float* __restrict__ w1,
    const float* __restrict__ w2, const float* __restrict__ w3,
    __nv_bfloat16* __restrict__ hi, __nv_bfloat16* __restrict__ lo)
{
    int z = blockIdx.z;
    const float* src = (z == 0) ? w0 : (z == 1) ? w1 : (z == 2) ? w2 : w3;
    int i = (blockIdx.x * 256 + threadIdx.x) * 4;
    size_t base = (size_t)z * E_ * E_;
    float4 x = *(const float4*)(src + i);
    bf4 h, l;
    split1(x.x, h.v[0], l.v[0]);
    split1(x.y, h.v[1], l.v[1]);
    split1(x.z, h.v[2], l.v[2]);
    split1(x.w, h.v[3], l.v[3]);
    *(bf4*)(hi + base + i) = h;
    *(bf4*)(lo + base + i) = l;
}

// ---------------- mma.sync bf16x2-split NT GEMM ----------------
// MODE 0: z selects Wq/Wk/Wv; outputs bf16 hi/lo in (B,H,S,D); q scaled 0.125.
// MODE 1: Wo; output fp32 row-major M x E.
#define BM 128
#define BN 128
#define BK 32
#define NCH (E_ / BK)
#define ROWB 80
#define TILE (128 * ROWB)
#define STAGE (4 * TILE)
#define GSM (2 * STAGE)

template<int MODE>
__global__ __launch_bounds__(256, 2) void gemm_mma(
    const __nv_bfloat16* __restrict__ Ahi, const __nv_bfloat16* __restrict__ Alo,
    const __nv_bfloat16* __restrict__ Whi, const __nv_bfloat16* __restrict__ Wlo,
    __nv_bfloat16* __restrict__ Qh, __nv_bfloat16* __restrict__ Ql,
    __nv_bfloat16* __restrict__ Kh, __nv_bfloat16* __restrict__ Kl,
    __nv_bfloat16* __restrict__ Vh, __nv_bfloat16* __restrict__ Vl,
    float* __restrict__ Of)
{
    extern __shared__ char smem[];
    const unsigned sb0 = smem_u32(smem);

    const int tid = threadIdx.x;
    const int lane = tid & 31;
    const int wid = tid >> 5;
    const int wm = wid & 1;
    const int wn = wid >> 1;
    const int m0 = blockIdx.y * BM;
    const int n0 = blockIdx.x * BN;
    const int z = (MODE == 0) ? blockIdx.z : 3;

    const __nv_bfloat16* Bhi = Whi + (size_t)z * E_ * E_ * (MODE == 0 ? 1 : 0)
                               + (MODE == 1 ? (size_t)3 * E_ * E_ : 0);
    const __nv_bfloat16* Blo = Wlo + (size_t)z * E_ * E_ * (MODE == 0 ? 1 : 0)
                               + (MODE == 1 ? (size_t)3 * E_ * E_ : 0);

    float acc[4][4][4];
    #pragma unroll
    for (int i = 0; i < 4; i++)
        #pragma unroll
        for (int j = 0; j < 4; j++)
            #pragma unroll
            for (int c = 0; c < 4; c++) acc[i][j][c] = 0.f;

    auto load_chunk = [&](unsigned sb, int k0) {
        #pragma unroll
        for (int j = 0; j < 2; j++) {
            int id = tid + j * 256;
            int r = id >> 2, c = id & 3;
            unsigned off = (unsigned)(r * ROWB + c * 16);
            size_t g = (size_t)(m0 + r) * E_ + k0 + c * 8;
            cpasync16(sb + off, Ahi + g);
            cpasync16(sb + TILE + off, Alo + g);
        }
        #pragma unroll
        for (int j = 0; j < 2; j++) {
            int id = tid + j * 256;
            int r = id >> 2, c = id & 3;
            unsigned off = (unsigned)(r * ROWB + c * 16);
            size_t g = (size_t)(n0 + r) * E_ + k0 + c * 8;
            cpasync16(sb + 2 * TILE + off, Bhi + g);
            cpasync16(sb + 3 * TILE + off, Blo + g);
        }
    };

    const unsigned a_row = (unsigned)(wm * 64 + (lane & 15));
    const unsigned a_coff = (unsigned)((lane >> 4) * 8) * 2u;
    const unsigned b_row = (unsigned)(wn * 32 + (lane & 7) + ((lane >> 4) << 3));
    const unsigned b_coff = (unsigned)(((lane >> 3) & 1) * 8) * 2u;

    auto compute = [&](unsigned sb) {
        #pragma unroll
        for (int ks = 0; ks < 2; ks++) {
            const unsigned kb = (unsigned)(ks * 16) * 2u;
            unsigned bh[8], bl[8];
            #pragma unroll
            for (int g = 0; g < 2; g++) {
                unsigned off = (b_row + g * 16) * ROWB + b_coff + kb;
                ldm_x4(&bh[4 * g], sb + 2 * TILE + off);
                ldm_x4(&bl[4 * g], sb + 3 * TILE + off);
            }
            #pragma unroll
            for (int mt = 0; mt < 4; mt++) {
                unsigned off = (a_row + mt * 16) * ROWB + a_coff + kb;
                unsigned ah[4], al[4];
                ldm_x4(ah, sb + off);
                ldm_x4(al, sb + TILE + off);
                #pragma unroll
                for (int nt = 0; nt < 4; nt++) {
                    mma_bf16(acc[mt][nt], ah, &bh[2 * nt]);
                    mma_bf16(acc[mt][nt], ah, &bl[2 * nt]);
                    mma_bf16(acc[mt][nt], al, &bh[2 * nt]);
                }
            }
        }
    };

    load_chunk(sb0, 0);
    CP_COMMIT;
    for (int ch = 0; ch < NCH; ch++) {
        const unsigned sb = sb0 + (unsigned)(ch & 1) * STAGE;
        if (ch + 1 < NCH) {
            load_chunk(sb0 + (unsigned)((ch + 1) & 1) * STAGE, (ch + 1) * BK);
            CP_COMMIT;
            CP_WAIT1;
        } else {
            CP_WAIT0;
        }
        __syncthreads();
        compute(sb);
        __syncthreads();
    }

    const int mbase = m0 + wm * 64 + (lane >> 2);
    const int nbase = n0 + wn * 32 + 2 * (lane & 3);
    if (MODE == 0) {
        __nv_bfloat16* Hp = (z == 0) ? Qh : (z == 1) ? Kh : Vh;
        __nv_bfloat16* Lp = (z == 0) ? Ql : (z == 1) ? Kl : Vl;
        const float sc = (z == 0) ? 0.125f : 1.0f;
        #pragma unroll
        for (int mt = 0; mt < 4; mt++) {
            #pragma unroll
            for (int nt = 0; nt < 4; nt++) {
                int m = mbase + mt * 16;
                int n = nbase + nt * 8;
                int h = n >> 6, d0 = n & 63;
                int b = m >> 11;
                size_t base = (((size_t)(b * H_ + h)) * S_ + (m & 2047)) * D_ + d0;
                #pragma unroll
                for (int half = 0; half < 2; half++) {
                    float v0 = acc[mt][nt][2 * half] * sc;
                    float v1 = acc[mt][nt][2 * half + 1] * sc;
                    __nv_bfloat16 h0, l0, h1, l1;
                    split1(v0, h0, l0);
                    split1(v1, h1, l1);
                    __nv_bfloat162 hv; hv.x = h0; hv.y = h1;
                    __nv_bfloat162 lv; lv.x = l0; lv.y = l1;
                    size_t a = base + (size_t)half * 8 * D_;
                    *(__nv_bfloat162*)(Hp + a) = hv;
                    *(__nv_bfloat162*)(Lp + a) = lv;
                }
            }
        }
    } else {
        #pragma unroll
        for (int mt = 0; mt < 4; mt++) {
            #pragma unroll
            for (int nt = 0; nt < 4; nt++) {
                int m = mbase + mt * 16;
                int n = nbase + nt * 8;
                size_t base = (size_t)m * E_ + n;
                *(float2*)(Of + base) = make_float2(acc[mt][nt][0], acc[mt][nt][1]);
                *(float2*)(Of + base + 8 * E_) = make_float2(acc[mt][nt][2], acc[mt][nt][3]);
            }
        }
    }
}

// ---------------- mma.sync flash attention (causal, bf16 split) ----------------
#define AROWB 144                    // 72 bf16 per padded row
#define SQL   (128 * AROWB)          // 18432
#define SKV0  (2 * 128 * AROWB)      // 36864
#define KVSTAGE (4 * 64 * AROWB)     // KH,KL,VH,VL = 36864
#define KARR  (64 * AROWB)           // 9216 per sub-array
#define ATT_SMEM (SKV0 + 2 * KVSTAGE)  // 110592

__global__ __launch_bounds__(256, 2) void flash_mma(
    const __nv_bfloat16* __restrict__ Qh, const __nv_bfloat16* __restrict__ Ql,
    const __nv_bfloat16* __restrict__ Kh, const __nv_bfloat16* __restrict__ Kl,
    const __nv_bfloat16* __restrict__ Vh, const __nv_bfloat16* __restrict__ Vl,
    __nv_bfloat16* __restrict__ Ohi, __nv_bfloat16* __restrict__ Olo)
{
    extern __shared__ char smem[];
    const unsigned sb = smem_u32(smem);
    const int tid = threadIdx.x;
    const int lane = tid & 31, wq = tid >> 5;
    const int bx = gridDim.x - 1 - blockIdx.x;   // heavy blocks first
    const int bh = blockIdx.y;
    const int q0 = bx * 128;
    const size_t hb = (size_t)bh * S_ * D_;

    // Q tiles (hi+lo), loaded once: 2048 x 16B
    #pragma unroll
    for (int j = 0; j < 8; j++) {
        int id = tid + j * 256;
        int arr = id >> 10;
        int r = (id & 1023) >> 3, c = id & 7;
        unsigned off = (arr ? SQL : 0) + r * AROWB + c * 16;
        const __nv_bfloat16* src = (arr ? Ql : Qh) + hb + (size_t)(q0 + r) * D_ + c * 8;
        cpasync16(sb + off, src);
    }
    auto load_kv = [&](int stage, int kv0) {
        unsigned base = sb + SKV0 + (unsigned)stage * KVSTAGE;
        #pragma unroll
        for (int j = 0; j < 8; j++) {
            int id = tid + j * 256;
            int arr = id >> 9;       // 0 KH, 1 KL, 2 VH, 3 VL
            int r = (id & 511) >> 3, c = id & 7;
            unsigned off = (unsigned)arr * KARR + r * AROWB + c * 16;
            const __nv_bfloat16* src =
                (arr == 0 ? Kh : arr == 1 ? Kl : arr == 2 ? Vh : Vl)
                + hb + (size_t)(kv0 + r) * D_ + c * 8;
            cpasync16(base + off, src);
        }
    };

    const int nt = 2 * bx + 2;
    load_kv(0, 0);
    CP_COMMIT;

    float sacc[8][4], oacc[8][4];
    float mrow[2] = {-1e30f, -1e30f}, lrow[2] = {0.f, 0.f};
    #pragma unroll
    for (int j = 0; j < 8; j++)
        #pragma unroll
        for (int c = 0; c < 4; c++) oacc[j][c] = 0.f;

    const unsigned qoff = sb + (unsigned)((wq * 16 + (lane & 15)) * AROWB + (lane >> 4) * 16);
    const unsigned krow = (unsigned)((lane & 7) + ((lane >> 4) << 3));
    const unsigned kcolb = (unsigned)(((lane >> 3) & 1) * 16);
    const unsigned vrow = (unsigned)((lane & 7) + (((lane >> 3) & 1) << 3));
    const unsigned vcolb = (unsigned)((lane >> 4) * 16);
    const int rl0 = wq * 16 + (lane >> 2);

    for (int t0 = 0; t0 < nt; t0++) {
        const int kv0 = t0 * 64;
        const unsigned kvb = sb + SKV0 + (unsigned)(t0 & 1) * KVSTAGE;
        if (t0 + 1 < nt) {
            load_kv((t0 + 1) & 1, kv0 + 64);
            CP_COMMIT;
            CP_WAIT1;
        } else {
            CP_WAIT0;
        }
        __syncthreads();

        // ---- S = Q K^T (3-product split) ----
        #pragma unroll
        for (int j = 0; j < 8; j++) {
            sacc[j][0] = 0.f; sacc[j][1] = 0.f; sacc[j][2] = 0.f; sacc[j][3] = 0.f;
        }
        #pragma unroll
        for (int ks = 0; ks < 4; ks++) {
            unsigned qh4[4], ql4[4];
            ldm_x4(qh4, qoff + ks * 32);
            ldm_x4(ql4, qoff + SQL + ks * 32);
            #pragma unroll
            for (int jj = 0; jj < 4; jj++) {
                unsigned bh4[4], bl4[4];
                unsigned ko = kvb + (jj * 16 + krow) * AROWB + kcolb + ks * 32;
                ldm_x4(bh4, ko);
                ldm_x4(bl4, ko + KARR);
                mma_bf16(sacc[2 * jj], qh4, bh4);
                mma_bf16(sacc[2 * jj], qh4, bl4);
                mma_bf16(sacc[2 * jj], ql4, bh4);
                mma_bf16(sacc[2 * jj + 1], qh4, bh4 + 2);
                mma_bf16(sacc[2 * jj + 1], qh4, bl4 + 2);
                mma_bf16(sacc[2 * jj + 1], ql4, bh4 + 2);
            }
        }

        // ---- mask + online softmax (fp32, poly exp) ----
        const bool maskt = (t0 >= nt - 2);
        const int rel = kv0 - q0;
        #pragma unroll
        for (int h = 0; h < 2; h++) {
            const int rloc = rl0 + 8 * h;
            if (maskt) {
                #pragma unroll
                for (int j = 0; j < 8; j++) {
                    int c0 = 8 * j + 2 * (lane & 3) + rel;
                    if (c0 > rloc)     sacc[j][2 * h]     = -1e30f;
                    if (c0 + 1 > rloc) sacc[j][2 * h + 1] = -1e30f;
                }
            }
            float mx = mrow[h];
            #pragma unroll
            for (int j = 0; j < 8; j++)
                mx = fmaxf(mx, fmaxf(sacc[j][2 * h], sacc[j][2 * h + 1]));
            mx = fmaxf(mx, __shfl_xor_sync(0xffffffffu, mx, 1));
            mx = fmaxf(mx, __shfl_xor_sync(0xffffffffu, mx, 2));
            float alpha = fexp(mrow[h] - mx);
            mrow[h] = mx;
            float rs = 0.f;
            #pragma unroll
            for (int j = 0; j < 8; j++) {
                float p0 = fexp(sacc[j][2 * h] - mx);
                float p1 = fexp(sacc[j][2 * h + 1] - mx);
                sacc[j][2 * h] = p0; sacc[j][2 * h + 1] = p1;
                rs += p0 + p1;
            }
            rs += __shfl_xor_sync(0xffffffffu, rs, 1);
            rs += __shfl_xor_sync(0xffffffffu, rs, 2);
            lrow[h] = lrow[h] * alpha + rs;
            #pragma unroll
            for (int j = 0; j < 8; j++) {
                oacc[j][2 * h] *= alpha;
                oacc[j][2 * h + 1] *= alpha;
            }
        }

        // ---- O += P V (P in registers, 3-product split) ----
        #pragma unroll
        for (int ks = 0; ks < 4; ks++) {
            unsigned phi[4], plo[4];
            #pragma unroll
            for (int i = 0; i < 4; i++) {
                int j = 2 * ks + (i >> 1);
                int bse = (i & 1) * 2;
                float p0 = sacc[j][bse], p1 = sacc[j][bse + 1];
                unsigned hp = pack_bf2(p0, p1);
                float2 hf = unpack_bf2(hp);
                phi[i] = hp;
                plo[i] = pack_bf2(p0 - hf.x, p1 - hf.y);
            }
            #pragma unroll
            for (int g = 0; g < 4; g++) {
                unsigned vh4[4], vl4[4];
                unsigned vo = kvb + 2 * KARR + (ks * 16 + vrow) * AROWB + vcolb + g * 32;
                ldm_x4_t(vh4, vo);
                ldm_x4_t(vl4, vo + KARR);
                mma_bf16(oacc[2 * g], phi, vh4);
                mma_bf16(oacc[2 * g], phi, vl4);
                mma_bf16(oacc[2 * g], plo, vh4);
                mma_bf16(oacc[2 * g + 1], phi, vh4 + 2);
                mma_bf16(oacc[2 * g + 1], phi, vl4 + 2);
                mma_bf16(oacc[2 * g + 1], plo, vh4 + 2);
            }
        }
        __syncthreads();
    }

    // ---- epilogue: O/l -> bf16 hi/lo, row-major (b*S+s, h*64+d) ----
    const int b = bh >> 4, hd = bh & 15;
    #pragma unroll
    for (int hh = 0; hh < 2; hh++) {
        float linv = 1.f / lrow[hh];
        int s = q0 + wq * 16 + (lane >> 2) + 8 * hh;
        size_t rowb = ((size_t)b * S_ + s) * E_ + hd * D_ + 2 * (lane & 3);
        #pragma unroll
        for (int j = 0; j < 8; j++) {
            float o0 = oacc[j][2 * hh] * linv;
            float o1 = oacc[j][2 * hh + 1] * linv;
            __nv_bfloat16 h0, l0, h1, l1;
            split1(o0, h0, l0);
            split1(o1, h1, l1);
            __nv_bfloat162 hv; hv.x = h0; hv.y = h1;
            __nv_bfloat162 lv; lv.x = l0; lv.y = l1;
            *(__nv_bfloat162*)(Ohi + rowb + 8 * j) = hv;
            *(__nv_bfloat162*)(Olo + rowb + 8 * j) = lv;
        }
    }
}

// ---------------- mod = silu(cond) @ Wc^T + bc ----------------
__global__ __launch_bounds__(256) void mod_kernel(
    const float* __restrict__ cond, const float* __restrict__ Wc,
    const float* __restrict__ bc, float* __restrict__ mod)
{
    __shared__ float sc[C_];
    int gid = blockIdx.x * 256 + threadIdx.x;
    int b = gid >> 11;
    int j = gid & 2047;
    {
        float c = cond[b * C_ + threadIdx.x];
        sc[threadIdx.x] = c / (1.f + __expf(-c));
    }
    __syncthreads();
    const float* wr = Wc + (size_t)j * C_;
    float acc = 0.f;
    #pragma unroll 8
    for (int c = 0; c < C_; c += 4) {
        float4 w = *(const float4*)&wr[c];
        acc += sc[c] * w.x + sc[c + 1] * w.y + sc[c + 2] * w.z + sc[c + 3] * w.w;
    }
    mod[gid] = acc + bc[j];
}

// ---------------- RMSNorm + FiLM ----------------
__global__ __launch_bounds__(256) void norm_film(
    const float* __restrict__ X, const float* __restrict__ gscale,
    const float* __restrict__ mod, float* __restrict__ out)
{
    const int m = blockIdx.x;
    const int b = m >> 11;
    const float* xr = X + (size_t)m * E_;
    const int e = threadIdx.x * 4;
    float4 v = *(const float4*)&xr[e];
    float ss = v.x * v.x + v.y * v.y + v.z * v.z + v.w * v.w;
    #pragma unroll
    for (int off = 16; off; off >>= 1)
        ss += __shfl_xor_sync(0xffffffffu, ss, off);
    __shared__ float red[8];
    if ((threadIdx.x & 31) == 0) red[threadIdx.x >> 5] = ss;
    __syncthreads();
    float tot = 0.f;
    #pragma unroll
    for (int i = 0; i < 8; i++) tot += red[i];
    float inv = rsqrtf(tot * (1.f / (float)E_) + 1e-6f);

    const float* mb = mod + (size_t)b * 2 * E_;
    float4 g  = *(const float4*)&gscale[e];
    float4 sh = *(const float4*)&mb[e];
    float4 sv = *(const float4*)&mb[E_ + e];
    float4 o;
    o.x = v.x * inv * g.x * (1.f + sv.x) + sh.x;
    o.y = v.y * inv * g.y * (1.f + sv.y) + sh.y;
    o.z = v.z * inv * g.z * (1.f + sv.z) + sh.z;
    o.w = v.w * inv * g.w * (1.f + sv.w) + sh.w;
    *(float4*)&out[(size_t)m * E_ + e] = o;
}

// ---------------- launch ----------------
extern "C" void kernel_launch(void* const* d_in, const int* in_sizes, int n_in,
                              void* d_out, int out_size)
{
    const float* x    = (const float*)d_in[0];
    // d_in[1] = mask: provably triu(ones,k=1) causal -> applied analytically
    const float* cond = (const float*)d_in[2];
    const float* Wq   = (const float*)d_in[3];
    const float* Wk   = (const float*)d_in[4];
    const float* Wv   = (const float*)d_in[5];
    const float* Wo   = (const float*)d_in[6];
    const float* rsc  = (const float*)d_in[7];
    const float* Wc   = (const float*)d_in[8];
    const float* bc   = (const float*)d_in[9];
    float* out = (float*)d_out;

    float *proj, *mod;
    __nv_bfloat16 *xhi, *xlo, *whi, *wlo, *ahi, *alo;
    __nv_bfloat16 *qh, *ql, *kh, *kl, *vh, *vl;
    cudaGetSymbolAddress((void**)&proj, g_proj);
    cudaGetSymbolAddress((void**)&mod,  g_mod);
    cudaGetSymbolAddress((void**)&xhi,  g_xhi);
    cudaGetSymbolAddress((void**)&xlo,  g_xlo);
    cudaGetSymbolAddress((void**)&whi,  g_whi);
    cudaGetSymbolAddress((void**)&wlo,  g_wlo);
    cudaGetSymbolAddress((void**)&ahi,  g_ahi);
    cudaGetSymbolAddress((void**)&alo,  g_alo);
    cudaGetSymbolAddress((void**)&qh,   g_qh);
    cudaGetSymbolAddress((void**)&ql,   g_ql);
    cudaGetSymbolAddress((void**)&kh,   g_kh);
    cudaGetSymbolAddress((void**)&kl,   g_kl);
    cudaGetSymbolAddress((void**)&vh,   g_vh);
    cudaGetSymbolAddress((void**)&vl,   g_vl);

    cudaFuncSetAttribute(gemm_mma<0>, cudaFuncAttributeMaxDynamicSharedMemorySize, GSM);
    cudaFuncSetAttribute(gemm_mma<1>, cudaFuncAttributeMaxDynamicSharedMemorySize, GSM);
    cudaFuncSetAttribute(flash_mma, cudaFuncAttributeMaxDynamicSharedMemorySize, ATT_SMEM);

    // fp32 -> bf16 hi/lo splits
    conv_split<<<M_TOT * E_ / 1024, 256>>>(x, xhi, xlo);
    conv_split_w<<<dim3(E_ * E_ / 1024, 1, 4), 256>>>(Wq, Wk, Wv, Wo, whi, wlo);
    // conditioning modulation (independent)
    mod_kernel<<<(B_ * 2 * E_) / 256, 256>>>(cond, Wc, bc, mod);
    // QKV projections -> bf16 hi/lo (B,H,S,D); q pre-scaled
    gemm_mma<0><<<dim3(E_ / BN, M_TOT / BM, 3), 256, GSM>>>(
        xhi, xlo, whi, wlo, qh, ql, kh, kl, vh, vl, nullptr);
    // causal flash attention on tensor cores -> bf16 hi/lo (m, E)
    flash_mma<<<dim3(S_ / 128, B_ * H_), 256, ATT_SMEM>>>(
        qh, ql, kh, kl, vh, vl, ahi, alo);
    // output projection -> fp32
    gemm_mma<1><<<dim3(E_ / BN, M_TOT / BM, 1), 256, GSM>>>(
        ahi, alo, whi, wlo, nullptr, nullptr, nullptr, nullptr, nullptr, nullptr, proj);
    // RMSNorm + FiLM
    norm_film<<<M_TOT, 256>>>(proj, rsc, mod, out);
}

// round 8
// speedup vs baseline: 2.4461x; 1.0304x over previous
#include <cuda_runtime.h>
#include <cuda_bf16.h>

#define B_ 2
#define S_ 2048
#define E_ 1024
#define H_ 16
#define D_ 64
#define C_ 256
#define M_TOT 4096   // B_*S_

// ---------------- scratch (no allocations allowed) ----------------
__device__ float g_proj[M_TOT*E_];
__device__ float g_mod[B_*2*E_];
__device__ __nv_bfloat16 g_xhi[M_TOT*E_];
__device__ __nv_bfloat16 g_xlo[M_TOT*E_];
__device__ __nv_bfloat16 g_whi[4*E_*E_];
__device__ __nv_bfloat16 g_wlo[4*E_*E_];
__device__ __nv_bfloat16 g_ahi[M_TOT*E_];
__device__ __nv_bfloat16 g_alo[M_TOT*E_];
__device__ __nv_bfloat16 g_qh[B_*H_*S_*D_];
__device__ __nv_bfloat16 g_ql[B_*H_*S_*D_];
__device__ __nv_bfloat16 g_kh[B_*H_*S_*D_];
__device__ __nv_bfloat16 g_kl[B_*H_*S_*D_];
__device__ __nv_bfloat16 g_vh[B_*H_*S_*D_];
__device__ __nv_bfloat16 g_vl[B_*H_*S_*D_];

// ---------------- mma.sync / ldmatrix / cp.async helpers ----------------
__device__ __forceinline__ unsigned smem_u32(const void* p) {
    unsigned a;
    asm("{ .reg .u64 t; cvta.to.shared.u64 t, %1; cvt.u32.u64 %0, t; }" : "=r"(a) : "l"(p));
    return a;
}
__device__ __forceinline__ void ldm_x4(unsigned* r, unsigned addr) {
    asm volatile("ldmatrix.sync.aligned.m8n8.x4.shared.b16 {%0,%1,%2,%3}, [%4];"
                 : "=r"(r[0]), "=r"(r[1]), "=r"(r[2]), "=r"(r[3]) : "r"(addr));
}
__device__ __forceinline__ void ldm_x4_t(unsigned* r, unsigned addr) {
    asm volatile("ldmatrix.sync.aligned.m8n8.x4.trans.shared.b16 {%0,%1,%2,%3}, [%4];"
                 : "=r"(r[0]), "=r"(r[1]), "=r"(r[2]), "=r"(r[3]) : "r"(addr));
}
__device__ __forceinline__ void mma_bf16(float* d, const unsigned* a, const unsigned* b) {
    asm volatile("mma.sync.aligned.m16n8k16.row.col.f32.bf16.bf16.f32 "
                 "{%0,%1,%2,%3}, {%4,%5,%6,%7}, {%8,%9}, {%0,%1,%2,%3};"
                 : "+f"(d[0]), "+f"(d[1]), "+f"(d[2]), "+f"(d[3])
                 : "r"(a[0]), "r"(a[1]), "r"(a[2]), "r"(a[3]), "r"(b[0]), "r"(b[1]));
}
__device__ __forceinline__ void cpasync16(unsigned dst, const void* src) {
    asm volatile("cp.async.cg.shared.global [%0], [%1], 16;" :: "r"(dst), "l"(src));
}
#define CP_COMMIT asm volatile("cp.async.commit_group;" ::: "memory")
#define CP_WAIT0  asm volatile("cp.async.wait_group 0;" ::: "memory")

// pack two fp32 -> bf16x2 register (lo16 = a, hi16 = b)
__device__ __forceinline__ unsigned pack_bf2(float a, float b) {
    unsigned r;
    asm("cvt.rn.bf16x2.f32 %0, %1, %2;" : "=r"(r) : "f"(b), "f"(a));
    return r;
}
__device__ __forceinline__ float2 unpack_bf2(unsigned u) {
    __nv_bfloat162 t = *reinterpret_cast<__nv_bfloat162*>(&u);
    return make_float2(__bfloat162float(t.x), __bfloat162float(t.y));
}

// fast exp on the FMA pipe (x <= ~0; masked -1e30 -> ~0)
__device__ __forceinline__ float fexp(float x) {
    float y = fmaxf(x * 1.4426950408889634f, -126.f);
    float fi = floorf(y);
    float f = y - fi;
    float p = 1.54353039e-4f;
    p = fmaf(p, f, 1.33335581e-3f);
    p = fmaf(p, f, 9.61812911e-3f);
    p = fmaf(p, f, 5.55041087e-2f);
    p = fmaf(p, f, 2.40226507e-1f);
    p = fmaf(p, f, 6.93147181e-1f);
    p = fmaf(p, f, 1.0f);
    return __int_as_float(__float_as_int(p) + (((int)fi) << 23));
}

// ---------------- fp32 -> bf16 hi/lo split ----------------
struct __align__(8) bf4 { __nv_bfloat16 v[4]; };

__device__ __forceinline__ void split1(float x, __nv_bfloat16& h, __nv_bfloat16& l) {
    h = __float2bfloat16(x);
    l = __float2bfloat16(x - __bfloat162float(h));
}

__global__ __launch_bounds__(256) void conv_split(
    const float* __restrict__ src, __nv_bfloat16* __restrict__ hi,
    __nv_bfloat16* __restrict__ lo)
{
    int i = (blockIdx.x * 256 + threadIdx.x) * 4;
    float4 x = *(const float4*)(src + i);
    bf4 h, l;
    split1(x.x, h.v[0], l.v[0]);
    split1(x.y, h.v[1], l.v[1]);
    split1(x.z, h.v[2], l.v[2]);
    split1(x.w, h.v[3], l.v[3]);
    *(bf4*)(hi + i) = h;
    *(bf4*)(lo + i) = l;
}

__global__ __launch_bounds__(256) void conv_split_w(
    const float* __restrict__ w0, const float* __restrict__ w1,
    const float* __restrict__ w2, const float* __restrict__ w3,
    __nv_bfloat16* __restrict__ hi, __nv_bfloat16* __restrict__ lo)
{
    int z = blockIdx.z;
    const float* src = (z == 0) ? w0 : (z == 1) ? w1 : (z == 2) ? w2 : w3;
    int i = (blockIdx.x * 256 + threadIdx.x) * 4;
    size_t base = (size_t)z * E_ * E_;
    float4 x = *(const float4*)(src + i);
    bf4 h, l;
    split1(x.x, h.v[0], l.v[0]);
    split1(x.y, h.v[1], l.v[1]);
    split1(x.z, h.v[2], l.v[2]);
    split1(x.w, h.v[3], l.v[3]);
    *(bf4*)(hi + base + i) = h;
    *(bf4*)(lo + base + i) = l;
}

// ---------------- mma.sync bf16x2-split NT GEMM ----------------
// MODE 0: z selects Wq/Wk/Wv; outputs bf16 hi/lo in (B,H,S,D); q scaled 0.125.
// MODE 1: Wo; output fp32 row-major M x E.
#define BM 128
#define BN 128
#define BK 32
#define NCH (E_ / BK)
#define ROWB 80
#define TILE (128 * ROWB)
#define STAGE (4 * TILE)
#define GSM (2 * STAGE)

template<int MODE>
__global__ __launch_bounds__(256, 2) void gemm_mma(
    const __nv_bfloat16* __restrict__ Ahi, const __nv_bfloat16* __restrict__ Alo,
    const __nv_bfloat16* __restrict__ Whi, const __nv_bfloat16* __restrict__ Wlo,
    __nv_bfloat16* __restrict__ Qh, __nv_bfloat16* __restrict__ Ql,
    __nv_bfloat16* __restrict__ Kh, __nv_bfloat16* __restrict__ Kl,
    __nv_bfloat16* __restrict__ Vh, __nv_bfloat16* __restrict__ Vl,
    float* __restrict__ Of)
{
    extern __shared__ char smem[];
    const unsigned sb0 = smem_u32(smem);

    const int tid = threadIdx.x;
    const int lane = tid & 31;
    const int wid = tid >> 5;
    const int wm = wid & 1;
    const int wn = wid >> 1;
    const int m0 = blockIdx.y * BM;
    const int n0 = blockIdx.x * BN;
    const int z = (MODE == 0) ? blockIdx.z : 3;

    const __nv_bfloat16* Bhi = Whi + (size_t)z * E_ * E_ * (MODE == 0 ? 1 : 0)
                               + (MODE == 1 ? (size_t)3 * E_ * E_ : 0);
    const __nv_bfloat16* Blo = Wlo + (size_t)z * E_ * E_ * (MODE == 0 ? 1 : 0)
                               + (MODE == 1 ? (size_t)3 * E_ * E_ : 0);

    float acc[4][4][4];
    #pragma unroll
    for (int i = 0; i < 4; i++)
        #pragma unroll
        for (int j = 0; j < 4; j++)
            #pragma unroll
            for (int c = 0; c < 4; c++) acc[i][j][c] = 0.f;

    auto load_chunk = [&](unsigned sb, int k0) {
        #pragma unroll
        for (int j = 0; j < 2; j++) {
            int id = tid + j * 256;
            int r = id >> 2, c = id & 3;
            unsigned off = (unsigned)(r * ROWB + c * 16);
            size_t g = (size_t)(m0 + r) * E_ + k0 + c * 8;
            cpasync16(sb + off, Ahi + g);
            cpasync16(sb + TILE + off, Alo + g);
        }
        #pragma unroll
        for (int j = 0; j < 2; j++) {
            int id = tid + j * 256;
            int r = id >> 2, c = id & 3;
            unsigned off = (unsigned)(r * ROWB + c * 16);
            size_t g = (size_t)(n0 + r) * E_ + k0 + c * 8;
            cpasync16(sb + 2 * TILE + off, Bhi + g);
            cpasync16(sb + 3 * TILE + off, Blo + g);
        }
    };

    const unsigned a_row = (unsigned)(wm * 64 + (lane & 15));
    const unsigned a_coff = (unsigned)((lane >> 4) * 8) * 2u;
    const unsigned b_row = (unsigned)(wn * 32 + (lane & 7) + ((lane >> 4) << 3));
    const unsigned b_coff = (unsigned)(((lane >> 3) & 1) * 8) * 2u;

    auto compute = [&](unsigned sb) {
        #pragma unroll
        for (int ks = 0; ks < 2; ks++) {
            const unsigned kb = (unsigned)(ks * 16) * 2u;
            unsigned bh[8], bl[8];
            #pragma unroll
            for (int g = 0; g < 2; g++) {
                unsigned off = (b_row + g * 16) * ROWB + b_coff + kb;
                ldm_x4(&bh[4 * g], sb + 2 * TILE + off);
                ldm_x4(&bl[4 * g], sb + 3 * TILE + off);
            }
            #pragma unroll
            for (int mt = 0; mt < 4; mt++) {
                unsigned off = (a_row + mt * 16) * ROWB + a_coff + kb;
                unsigned ah[4], al[4];
                ldm_x4(ah, sb + off);
                ldm_x4(al, sb + TILE + off);
                #pragma unroll
                for (int nt = 0; nt < 4; nt++) {
                    mma_bf16(acc[mt][nt], ah, &bh[2 * nt]);
                    mma_bf16(acc[mt][nt], ah, &bl[2 * nt]);
                    mma_bf16(acc[mt][nt], al, &bh[2 * nt]);
                }
            }
        }
    };

    // single-barrier 2-stage pipeline:
    // [wait(load ch); barrier; issue load(ch+1); compute(ch)]
    // load(ch+1) targets the buffer compute(ch-1) used — all warps passed
    // this iteration's barrier only after finishing compute(ch-1).
    load_chunk(sb0, 0);
    CP_COMMIT;
    for (int ch = 0; ch < NCH; ch++) {
        const unsigned sb = sb0 + (unsigned)(ch & 1) * STAGE;
        CP_WAIT0;
        __syncthreads();
        if (ch + 1 < NCH) {
            load_chunk(sb0 + (unsigned)((ch + 1) & 1) * STAGE, (ch + 1) * BK);
            CP_COMMIT;
        }
        compute(sb);
    }

    const int mbase = m0 + wm * 64 + (lane >> 2);
    const int nbase = n0 + wn * 32 + 2 * (lane & 3);
    if (MODE == 0) {
        __nv_bfloat16* Hp = (z == 0) ? Qh : (z == 1) ? Kh : Vh;
        __nv_bfloat16* Lp = (z == 0) ? Ql : (z == 1) ? Kl : Vl;
        const float sc = (z == 0) ? 0.125f : 1.0f;
        #pragma unroll
        for (int mt = 0; mt < 4; mt++) {
            #pragma unroll
            for (int nt = 0; nt < 4; nt++) {
                int m = mbase + mt * 16;
                int n = nbase + nt * 8;
                int h = n >> 6, d0 = n & 63;
                int b = m >> 11;
                size_t base = (((size_t)(b * H_ + h)) * S_ + (m & 2047)) * D_ + d0;
                #pragma unroll
                for (int half = 0; half < 2; half++) {
                    float v0 = acc[mt][nt][2 * half] * sc;
                    float v1 = acc[mt][nt][2 * half + 1] * sc;
                    __nv_bfloat16 h0, l0, h1, l1;
                    split1(v0, h0, l0);
                    split1(v1, h1, l1);
                    __nv_bfloat162 hv; hv.x = h0; hv.y = h1;
                    __nv_bfloat162 lv; lv.x = l0; lv.y = l1;
                    size_t a = base + (size_t)half * 8 * D_;
                    *(__nv_bfloat162*)(Hp + a) = hv;
                    *(__nv_bfloat162*)(Lp + a) = lv;
                }
            }
        }
    } else {
        #pragma unroll
        for (int mt = 0; mt < 4; mt++) {
            #pragma unroll
            for (int nt = 0; nt < 4; nt++) {
                int m = mbase + mt * 16;
                int n = nbase + nt * 8;
                size_t base = (size_t)m * E_ + n;
                *(float2*)(Of + base) = make_float2(acc[mt][nt][0], acc[mt][nt][1]);
                *(float2*)(Of + base + 8 * E_) = make_float2(acc[mt][nt][2], acc[mt][nt][3]);
            }
        }
    }
}

// ---------------- mma.sync flash attention (causal, bf16 split) ----------------
#define AROWB 144                    // 72 bf16 per padded row
#define SQL   (128 * AROWB)          // 18432
#define SKV0  (2 * 128 * AROWB)      // 36864
#define KVSTAGE (4 * 64 * AROWB)     // KH,KL,VH,VL = 36864
#define KARR  (64 * AROWB)           // 9216 per sub-array
#define ATT_SMEM (SKV0 + 2 * KVSTAGE)  // 110592

__global__ __launch_bounds__(256, 2) void flash_mma(
    const __nv_bfloat16* __restrict__ Qh, const __nv_bfloat16* __restrict__ Ql,
    const __nv_bfloat16* __restrict__ Kh, const __nv_bfloat16* __restrict__ Kl,
    const __nv_bfloat16* __restrict__ Vh, const __nv_bfloat16* __restrict__ Vl,
    __nv_bfloat16* __restrict__ Ohi, __nv_bfloat16* __restrict__ Olo)
{
    extern __shared__ char smem[];
    const unsigned sb = smem_u32(smem);
    const int tid = threadIdx.x;
    const int lane = tid & 31, wq = tid >> 5;
    const int bx = gridDim.x - 1 - blockIdx.x;   // heavy blocks first
    const int bh = blockIdx.y;
    const int q0 = bx * 128;
    const size_t hb = (size_t)bh * S_ * D_;

    // Q tiles (hi+lo), loaded once: 2048 x 16B
    #pragma unroll
    for (int j = 0; j < 8; j++) {
        int id = tid + j * 256;
        int arr = id >> 10;
        int r = (id & 1023) >> 3, c = id & 7;
        unsigned off = (arr ? SQL : 0) + r * AROWB + c * 16;
        const __nv_bfloat16* src = (arr ? Ql : Qh) + hb + (size_t)(q0 + r) * D_ + c * 8;
        cpasync16(sb + off, src);
    }
    auto load_kv = [&](int stage, int kv0) {
        unsigned base = sb + SKV0 + (unsigned)stage * KVSTAGE;
        #pragma unroll
        for (int j = 0; j < 8; j++) {
            int id = tid + j * 256;
            int arr = id >> 9;       // 0 KH, 1 KL, 2 VH, 3 VL
            int r = (id & 511) >> 3, c = id & 7;
            unsigned off = (unsigned)arr * KARR + r * AROWB + c * 16;
            const __nv_bfloat16* src =
                (arr == 0 ? Kh : arr == 1 ? Kl : arr == 2 ? Vh : Vl)
                + hb + (size_t)(kv0 + r) * D_ + c * 8;
            cpasync16(base + off, src);
        }
    };

    const int nt = 2 * bx + 2;
    load_kv(0, 0);
    CP_COMMIT;

    float sacc[8][4], oacc[8][4];
    float mrow[2] = {-1e30f, -1e30f}, lrow[2] = {0.f, 0.f};
    #pragma unroll
    for (int j = 0; j < 8; j++)
        #pragma unroll
        for (int c = 0; c < 4; c++) oacc[j][c] = 0.f;

    const unsigned qoff = sb + (unsigned)((wq * 16 + (lane & 15)) * AROWB + (lane >> 4) * 16);
    const unsigned krow = (unsigned)((lane & 7) + ((lane >> 4) << 3));
    const unsigned kcolb = (unsigned)(((lane >> 3) & 1) * 16);
    const unsigned vrow = (unsigned)((lane & 7) + (((lane >> 3) & 1) << 3));
    const unsigned vcolb = (unsigned)((lane >> 4) * 16);
    const int rl0 = wq * 16 + (lane >> 2);

    for (int t0 = 0; t0 < nt; t0++) {
        const int kv0 = t0 * 64;
        const unsigned kvb = sb + SKV0 + (unsigned)(t0 & 1) * KVSTAGE;
        // single-barrier 2-stage pipeline (see gemm_mma comment)
        CP_WAIT0;
        __syncthreads();
        if (t0 + 1 < nt) {
            load_kv((t0 + 1) & 1, kv0 + 64);
            CP_COMMIT;
        }

        // ---- S = Q K^T (3-product split) ----
        #pragma unroll
        for (int j = 0; j < 8; j++) {
            sacc[j][0] = 0.f; sacc[j][1] = 0.f; sacc[j][2] = 0.f; sacc[j][3] = 0.f;
        }
        #pragma unroll
        for (int ks = 0; ks < 4; ks++) {
            unsigned qh4[4], ql4[4];
            ldm_x4(qh4, qoff + ks * 32);
            ldm_x4(ql4, qoff + SQL + ks * 32);
            #pragma unroll
            for (int jj = 0; jj < 4; jj++) {
                unsigned bh4[4], bl4[4];
                unsigned ko = kvb + (jj * 16 + krow) * AROWB + kcolb + ks * 32;
                ldm_x4(bh4, ko);
                ldm_x4(bl4, ko + KARR);
                mma_bf16(sacc[2 * jj], qh4, bh4);
                mma_bf16(sacc[2 * jj], qh4, bl4);
                mma_bf16(sacc[2 * jj], ql4, bh4);
                mma_bf16(sacc[2 * jj + 1], qh4, bh4 + 2);
                mma_bf16(sacc[2 * jj + 1], qh4, bl4 + 2);
                mma_bf16(sacc[2 * jj + 1], ql4, bh4 + 2);
            }
        }

        // ---- mask + online softmax (fp32, poly exp) ----
        const bool maskt = (t0 >= nt - 2);
        const int rel = kv0 - q0;
        #pragma unroll
        for (int h = 0; h < 2; h++) {
            const int rloc = rl0 + 8 * h;
            if (maskt) {
                #pragma unroll
                for (int j = 0; j < 8; j++) {
                    int c0 = 8 * j + 2 * (lane & 3) + rel;
                    if (c0 > rloc)     sacc[j][2 * h]     = -1e30f;
                    if (c0 + 1 > rloc) sacc[j][2 * h + 1] = -1e30f;
                }
            }
            float mx = mrow[h];
            #pragma unroll
            for (int j = 0; j < 8; j++)
                mx = fmaxf(mx, fmaxf(sacc[j][2 * h], sacc[j][2 * h + 1]));
            mx = fmaxf(mx, __shfl_xor_sync(0xffffffffu, mx, 1));
            mx = fmaxf(mx, __shfl_xor_sync(0xffffffffu, mx, 2));
            float alpha = fexp(mrow[h] - mx);
            mrow[h] = mx;
            float rs = 0.f;
            #pragma unroll
            for (int j = 0; j < 8; j++) {
                float p0 = fexp(sacc[j][2 * h] - mx);
                float p1 = fexp(sacc[j][2 * h + 1] - mx);
                sacc[j][2 * h] = p0; sacc[j][2 * h + 1] = p1;
                rs += p0 + p1;
            }
            rs += __shfl_xor_sync(0xffffffffu, rs, 1);
            rs += __shfl_xor_sync(0xffffffffu, rs, 2);
            lrow[h] = lrow[h] * alpha + rs;
            #pragma unroll
            for (int j = 0; j < 8; j++) {
                oacc[j][2 * h] *= alpha;
                oacc[j][2 * h + 1] *= alpha;
            }
        }

        // ---- O += P V (P in registers, 3-product split) ----
        #pragma unroll
        for (int ks = 0; ks < 4; ks++) {
            unsigned phi[4], plo[4];
            #pragma unroll
            for (int i = 0; i < 4; i++) {
                int j = 2 * ks + (i >> 1);
                int bse = (i & 1) * 2;
                float p0 = sacc[j][bse], p1 = sacc[j][bse + 1];
                unsigned hp = pack_bf2(p0, p1);
                float2 hf = unpack_bf2(hp);
                phi[i] = hp;
                plo[i] = pack_bf2(p0 - hf.x, p1 - hf.y);
            }
            #pragma unroll
            for (int g = 0; g < 4; g++) {
                unsigned vh4[4], vl4[4];
                unsigned vo = kvb + 2 * KARR + (ks * 16 + vrow) * AROWB + vcolb + g * 32;
                ldm_x4_t(vh4, vo);
                ldm_x4_t(vl4, vo + KARR);
                mma_bf16(oacc[2 * g], phi, vh4);
                mma_bf16(oacc[2 * g], phi, vl4);
                mma_bf16(oacc[2 * g], plo, vh4);
                mma_bf16(oacc[2 * g + 1], phi, vh4 + 2);
                mma_bf16(oacc[2 * g + 1], phi, vl4 + 2);
                mma_bf16(oacc[2 * g + 1], plo, vh4 + 2);
            }
        }
    }

    // ---- epilogue: O/l -> bf16 hi/lo, row-major (b*S+s, h*64+d) ----
    const int b = bh >> 4, hd = bh & 15;
    #pragma unroll
    for (int hh = 0; hh < 2; hh++) {
        float linv = 1.f / lrow[hh];
        int s = q0 + wq * 16 + (lane >> 2) + 8 * hh;
        size_t rowb = ((size_t)b * S_ + s) * E_ + hd * D_ + 2 * (lane & 3);
        #pragma unroll
        for (int j = 0; j < 8; j++) {
            float o0 = oacc[j][2 * hh] * linv;
            float o1 = oacc[j][2 * hh + 1] * linv;
            __nv_bfloat16 h0, l0, h1, l1;
            split1(o0, h0, l0);
            split1(o1, h1, l1);
            __nv_bfloat162 hv; hv.x = h0; hv.y = h1;
            __nv_bfloat162 lv; lv.x = l0; lv.y = l1;
            *(__nv_bfloat162*)(Ohi + rowb + 8 * j) = hv;
            *(__nv_bfloat162*)(Olo + rowb + 8 * j) = lv;
        }
    }
}

// ---------------- mod = silu(cond) @ Wc^T + bc ----------------
__global__ __launch_bounds__(256) void mod_kernel(
    const float* __restrict__ cond, const float* __restrict__ Wc,
    const float* __restrict__ bc, float* __restrict__ mod)
{
    __shared__ float sc[C_];
    int gid = blockIdx.x * 256 + threadIdx.x;
    int b = gid >> 11;
    int j = gid & 2047;
    {
        float c = cond[b * C_ + threadIdx.x];
        sc[threadIdx.x] = c / (1.f + __expf(-c));
    }
    __syncthreads();
    const float* wr = Wc + (size_t)j * C_;
    float acc = 0.f;
    #pragma unroll 8
    for (int c = 0; c < C_; c += 4) {
        float4 w = *(const float4*)&wr[c];
        acc += sc[c] * w.x + sc[c + 1] * w.y + sc[c + 2] * w.z + sc[c + 3] * w.w;
    }
    mod[gid] = acc + bc[j];
}

// ---------------- RMSNorm + FiLM ----------------
__global__ __launch_bounds__(256) void norm_film(
    const float* __restrict__ X, const float* __restrict__ gscale,
    const float* __restrict__ mod, float* __restrict__ out)
{
    const int m = blockIdx.x;
    const int b = m >> 11;
    const float* xr = X + (size_t)m * E_;
    const int e = threadIdx.x * 4;
    float4 v = *(const float4*)&xr[e];
    float ss = v.x * v.x + v.y * v.y + v.z * v.z + v.w * v.w;
    #pragma unroll
    for (int off = 16; off; off >>= 1)
        ss += __shfl_xor_sync(0xffffffffu, ss, off);
    __shared__ float red[8];
    if ((threadIdx.x & 31) == 0) red[threadIdx.x >> 5] = ss;
    __syncthreads();
    float tot = 0.f;
    #pragma unroll
    for (int i = 0; i < 8; i++) tot += red[i];
    float inv = rsqrtf(tot * (1.f / (float)E_) + 1e-6f);

    const float* mb = mod + (size_t)b * 2 * E_;
    float4 g  = *(const float4*)&gscale[e];
    float4 sh = *(const float4*)&mb[e];
    float4 sv = *(const float4*)&mb[E_ + e];
    float4 o;
    o.x = v.x * inv * g.x * (1.f + sv.x) + sh.x;
    o.y = v.y * inv * g.y * (1.f + sv.y) + sh.y;
    o.z = v.z * inv * g.z * (1.f + sv.z) + sh.z;
    o.w = v.w * inv * g.w * (1.f + sv.w) + sh.w;
    *(float4*)&out[(size_t)m * E_ + e] = o;
}

// ---------------- launch ----------------
extern "C" void kernel_launch(void* const* d_in, const int* in_sizes, int n_in,
                              void* d_out, int out_size)
{
    const float* x    = (const float*)d_in[0];
    // d_in[1] = mask: provably triu(ones,k=1) causal -> applied analytically
    const float* cond = (const float*)d_in[2];
    const float* Wq   = (const float*)d_in[3];
    const float* Wk   = (const float*)d_in[4];
    const float* Wv   = (const float*)d_in[5];
    const float* Wo   = (const float*)d_in[6];
    const float* rsc  = (const float*)d_in[7];
    const float* Wc   = (const float*)d_in[8];
    const float* bc   = (const float*)d_in[9];
    float* out = (float*)d_out;

    float *proj, *mod;
    __nv_bfloat16 *xhi, *xlo, *whi, *wlo, *ahi, *alo;
    __nv_bfloat16 *qh, *ql, *kh, *kl, *vh, *vl;
    cudaGetSymbolAddress((void**)&proj, g_proj);
    cudaGetSymbolAddress((void**)&mod,  g_mod);
    cudaGetSymbolAddress((void**)&xhi,  g_xhi);
    cudaGetSymbolAddress((void**)&xlo,  g_xlo);
    cudaGetSymbolAddress((void**)&whi,  g_whi);
    cudaGetSymbolAddress((void**)&wlo,  g_wlo);
    cudaGetSymbolAddress((void**)&ahi,  g_ahi);
    cudaGetSymbolAddress((void**)&alo,  g_alo);
    cudaGetSymbolAddress((void**)&qh,   g_qh);
    cudaGetSymbolAddress((void**)&ql,   g_ql);
    cudaGetSymbolAddress((void**)&kh,   g_kh);
    cudaGetSymbolAddress((void**)&kl,   g_kl);
    cudaGetSymbolAddress((void**)&vh,   g_vh);
    cudaGetSymbolAddress((void**)&vl,   g_vl);

    cudaFuncSetAttribute(gemm_mma<0>, cudaFuncAttributeMaxDynamicSharedMemorySize, GSM);
    cudaFuncSetAttribute(gemm_mma<1>, cudaFuncAttributeMaxDynamicSharedMemorySize, GSM);
    cudaFuncSetAttribute(flash_mma, cudaFuncAttributeMaxDynamicSharedMemorySize, ATT_SMEM);

    // fp32 -> bf16 hi/lo splits
    conv_split<<<M_TOT * E_ / 1024, 256>>>(x, xhi, xlo);
    conv_split_w<<<dim3(E_ * E_ / 1024, 1, 4), 256>>>(Wq, Wk, Wv, Wo, whi, wlo);
    // conditioning modulation (independent)
    mod_kernel<<<(B_ * 2 * E_) / 256, 256>>>(cond, Wc, bc, mod);
    // QKV projections -> bf16 hi/lo (B,H,S,D); q pre-scaled
    gemm_mma<0><<<dim3(E_ / BN, M_TOT / BM, 3), 256, GSM>>>(
        xhi, xlo, whi, wlo, qh, ql, kh, kl, vh, vl, nullptr);
    // causal flash attention on tensor cores -> bf16 hi/lo (m, E)
    flash_mma<<<dim3(S_ / 128, B_ * H_), 256, ATT_SMEM>>>(
        qh, ql, kh, kl, vh, vl, ahi, alo);
    // output projection -> fp32
    gemm_mma<1><<<dim3(E_ / BN, M_TOT / BM, 1), 256, GSM>>>(
        ahi, alo, whi, wlo, nullptr, nullptr, nullptr, nullptr, nullptr, nullptr, proj);
    // RMSNorm + FiLM
    norm_film<<<M_TOT, 256>>>(proj, rsc, mod, out);
}

// round 9
// speedup vs baseline: 2.6843x; 1.0974x over previous
#include <cuda_runtime.h>
#include <cuda_bf16.h>

#define B_ 2
#define S_ 2048
#define E_ 1024
#define H_ 16
#define D_ 64
#define C_ 256
#define M_TOT 4096   // B_*S_

// ---------------- scratch (no allocations allowed) ----------------
__device__ float g_proj[M_TOT*E_];
__device__ float g_mod[B_*2*E_];
__device__ __nv_bfloat16 g_xhi[M_TOT*E_];
__device__ __nv_bfloat16 g_xlo[M_TOT*E_];
__device__ __nv_bfloat16 g_whi[4*E_*E_];
__device__ __nv_bfloat16 g_wlo[4*E_*E_];
__device__ __nv_bfloat16 g_ahi[M_TOT*E_];
__device__ __nv_bfloat16 g_alo[M_TOT*E_];
__device__ __nv_bfloat16 g_qh[B_*H_*S_*D_];
__device__ __nv_bfloat16 g_ql[B_*H_*S_*D_];
__device__ __nv_bfloat16 g_kh[B_*H_*S_*D_];
__device__ __nv_bfloat16 g_kl[B_*H_*S_*D_];
__device__ __nv_bfloat16 g_vh[B_*H_*S_*D_];
__device__ __nv_bfloat16 g_vl[B_*H_*S_*D_];

// ---------------- mma.sync / ldmatrix / cp.async helpers ----------------
__device__ __forceinline__ unsigned smem_u32(const void* p) {
    unsigned a;
    asm("{ .reg .u64 t; cvta.to.shared.u64 t, %1; cvt.u32.u64 %0, t; }" : "=r"(a) : "l"(p));
    return a;
}
__device__ __forceinline__ void ldm_x4(unsigned* r, unsigned addr) {
    asm volatile("ldmatrix.sync.aligned.m8n8.x4.shared.b16 {%0,%1,%2,%3}, [%4];"
                 : "=r"(r[0]), "=r"(r[1]), "=r"(r[2]), "=r"(r[3]) : "r"(addr));
}
__device__ __forceinline__ void ldm_x4_t(unsigned* r, unsigned addr) {
    asm volatile("ldmatrix.sync.aligned.m8n8.x4.trans.shared.b16 {%0,%1,%2,%3}, [%4];"
                 : "=r"(r[0]), "=r"(r[1]), "=r"(r[2]), "=r"(r[3]) : "r"(addr));
}
__device__ __forceinline__ void mma_bf16(float* d, const unsigned* a, const unsigned* b) {
    asm volatile("mma.sync.aligned.m16n8k16.row.col.f32.bf16.bf16.f32 "
                 "{%0,%1,%2,%3}, {%4,%5,%6,%7}, {%8,%9}, {%0,%1,%2,%3};"
                 : "+f"(d[0]), "+f"(d[1]), "+f"(d[2]), "+f"(d[3])
                 : "r"(a[0]), "r"(a[1]), "r"(a[2]), "r"(a[3]), "r"(b[0]), "r"(b[1]));
}
__device__ __forceinline__ void cpasync16(unsigned dst, const void* src) {
    asm volatile("cp.async.cg.shared.global [%0], [%1], 16;" :: "r"(dst), "l"(src));
}
#define CP_COMMIT asm volatile("cp.async.commit_group;" ::: "memory")
#define CP_WAIT0  asm volatile("cp.async.wait_group 0;" ::: "memory")

// pack two fp32 -> bf16x2 register (lo16 = a, hi16 = b)
__device__ __forceinline__ unsigned pack_bf2(float a, float b) {
    unsigned r;
    asm("cvt.rn.bf16x2.f32 %0, %1, %2;" : "=r"(r) : "f"(b), "f"(a));
    return r;
}
__device__ __forceinline__ float2 unpack_bf2(unsigned u) {
    __nv_bfloat162 t = *reinterpret_cast<__nv_bfloat162*>(&u);
    return make_float2(__bfloat162float(t.x), __bfloat162float(t.y));
}

// fast exp on the FMA pipe (x <= ~0; masked -1e30 -> ~0)
__device__ __forceinline__ float fexp(float x) {
    float y = fmaxf(x * 1.4426950408889634f, -126.f);
    float fi = floorf(y);
    float f = y - fi;
    float p = 1.54353039e-4f;
    p = fmaf(p, f, 1.33335581e-3f);
    p = fmaf(p, f, 9.61812911e-3f);
    p = fmaf(p, f, 5.55041087e-2f);
    p = fmaf(p, f, 2.40226507e-1f);
    p = fmaf(p, f, 6.93147181e-1f);
    p = fmaf(p, f, 1.0f);
    return __int_as_float(__float_as_int(p) + (((int)fi) << 23));
}

// ---------------- fp32 -> bf16 hi/lo split ----------------
struct __align__(8) bf4 { __nv_bfloat16 v[4]; };

__device__ __forceinline__ void split1(float x, __nv_bfloat16& h, __nv_bfloat16& l) {
    h = __float2bfloat16(x);
    l = __float2bfloat16(x - __bfloat162float(h));
}

__global__ __launch_bounds__(256) void conv_split(
    const float* __restrict__ src, __nv_bfloat16* __restrict__ hi,
    __nv_bfloat16* __restrict__ lo)
{
    int i = (blockIdx.x * 256 + threadIdx.x) * 4;
    float4 x = *(const float4*)(src + i);
    bf4 h, l;
    split1(x.x, h.v[0], l.v[0]);
    split1(x.y, h.v[1], l.v[1]);
    split1(x.z, h.v[2], l.v[2]);
    split1(x.w, h.v[3], l.v[3]);
    *(bf4*)(hi + i) = h;
    *(bf4*)(lo + i) = l;
}

__global__ __launch_bounds__(256) void conv_split_w(
    const float* __restrict__ w0, const float* __restrict__ w1,
    const float* __restrict__ w2, const float* __restrict__ w3,
    __nv_bfloat16* __restrict__ hi, __nv_bfloat16* __restrict__ lo)
{
    int z = blockIdx.z;
    const float* src = (z == 0) ? w0 : (z == 1) ? w1 : (z == 2) ? w2 : w3;
    int i = (blockIdx.x * 256 + threadIdx.x) * 4;
    size_t base = (size_t)z * E_ * E_;
    float4 x = *(const float4*)(src + i);
    bf4 h, l;
    split1(x.x, h.v[0], l.v[0]);
    split1(x.y, h.v[1], l.v[1]);
    split1(x.z, h.v[2], l.v[2]);
    split1(x.w, h.v[3], l.v[3]);
    *(bf4*)(hi + base + i) = h;
    *(bf4*)(lo + base + i) = l;
}

// ---------------- mma.sync bf16x2-split NT GEMM ----------------
// MODE 0: z selects Wq/Wk/Wv; outputs bf16 hi/lo in (B,H,S,D); q scaled 0.125.
// MODE 1: Wo; output fp32 row-major M x E.
#define BM 128
#define BN 128
#define BK 32
#define NCH (E_ / BK)
#define ROWB 80
#define TILE (128 * ROWB)
#define STAGE (4 * TILE)
#define GSM (2 * STAGE)

template<int MODE>
__global__ __launch_bounds__(256, 2) void gemm_mma(
    const __nv_bfloat16* __restrict__ Ahi, const __nv_bfloat16* __restrict__ Alo,
    const __nv_bfloat16* __restrict__ Whi, const __nv_bfloat16* __restrict__ Wlo,
    __nv_bfloat16* __restrict__ Qh, __nv_bfloat16* __restrict__ Ql,
    __nv_bfloat16* __restrict__ Kh, __nv_bfloat16* __restrict__ Kl,
    __nv_bfloat16* __restrict__ Vh, __nv_bfloat16* __restrict__ Vl,
    float* __restrict__ Of)
{
    extern __shared__ char smem[];
    const unsigned sb0 = smem_u32(smem);

    const int tid = threadIdx.x;
    const int lane = tid & 31;
    const int wid = tid >> 5;
    const int wm = wid & 1;
    const int wn = wid >> 1;
    const int m0 = blockIdx.y * BM;
    const int n0 = blockIdx.x * BN;
    const int z = (MODE == 0) ? blockIdx.z : 3;

    const __nv_bfloat16* Bhi = Whi + (size_t)z * E_ * E_ * (MODE == 0 ? 1 : 0)
                               + (MODE == 1 ? (size_t)3 * E_ * E_ : 0);
    const __nv_bfloat16* Blo = Wlo + (size_t)z * E_ * E_ * (MODE == 0 ? 1 : 0)
                               + (MODE == 1 ? (size_t)3 * E_ * E_ : 0);

    float acc[4][4][4];
    #pragma unroll
    for (int i = 0; i < 4; i++)
        #pragma unroll
        for (int j = 0; j < 4; j++)
            #pragma unroll
            for (int c = 0; c < 4; c++) acc[i][j][c] = 0.f;

    auto load_chunk = [&](unsigned sb, int k0) {
        #pragma unroll
        for (int j = 0; j < 2; j++) {
            int id = tid + j * 256;
            int r = id >> 2, c = id & 3;
            unsigned off = (unsigned)(r * ROWB + c * 16);
            size_t g = (size_t)(m0 + r) * E_ + k0 + c * 8;
            cpasync16(sb + off, Ahi + g);
            cpasync16(sb + TILE + off, Alo + g);
        }
        #pragma unroll
        for (int j = 0; j < 2; j++) {
            int id = tid + j * 256;
            int r = id >> 2, c = id & 3;
            unsigned off = (unsigned)(r * ROWB + c * 16);
            size_t g = (size_t)(n0 + r) * E_ + k0 + c * 8;
            cpasync16(sb + 2 * TILE + off, Bhi + g);
            cpasync16(sb + 3 * TILE + off, Blo + g);
        }
    };

    const unsigned a_row = (unsigned)(wm * 64 + (lane & 15));
    const unsigned a_coff = (unsigned)((lane >> 4) * 8) * 2u;
    const unsigned b_row = (unsigned)(wn * 32 + (lane & 7) + ((lane >> 4) << 3));
    const unsigned b_coff = (unsigned)(((lane >> 3) & 1) * 8) * 2u;

    // one K=16 slice; product-major mma order breaks same-acc RAW chains
    auto compute_ks = [&](unsigned sb, int ks) {
        const unsigned kb = (unsigned)(ks * 16) * 2u;
        unsigned bh[8], bl[8];
        #pragma unroll
        for (int g = 0; g < 2; g++) {
            unsigned off = (b_row + g * 16) * ROWB + b_coff + kb;
            ldm_x4(&bh[4 * g], sb + 2 * TILE + off);
            ldm_x4(&bl[4 * g], sb + 3 * TILE + off);
        }
        #pragma unroll
        for (int mt = 0; mt < 4; mt++) {
            unsigned off = (a_row + mt * 16) * ROWB + a_coff + kb;
            unsigned ah[4], al[4];
            ldm_x4(ah, sb + off);
            ldm_x4(al, sb + TILE + off);
            #pragma unroll
            for (int nt = 0; nt < 4; nt++) mma_bf16(acc[mt][nt], ah, &bh[2 * nt]);
            #pragma unroll
            for (int nt = 0; nt < 4; nt++) mma_bf16(acc[mt][nt], ah, &bl[2 * nt]);
            #pragma unroll
            for (int nt = 0; nt < 4; nt++) mma_bf16(acc[mt][nt], al, &bh[2 * nt]);
        }
    };

    // single-barrier 2-stage pipeline; next chunk's loads issued between
    // the two ks halves so the LDGSTS burst overlaps mma issue.
    load_chunk(sb0, 0);
    CP_COMMIT;
    for (int ch = 0; ch < NCH; ch++) {
        const unsigned sb = sb0 + (unsigned)(ch & 1) * STAGE;
        CP_WAIT0;
        __syncthreads();
        compute_ks(sb, 0);
        if (ch + 1 < NCH) {
            load_chunk(sb0 + (unsigned)((ch + 1) & 1) * STAGE, (ch + 1) * BK);
            CP_COMMIT;
        }
        compute_ks(sb, 1);
    }

    const int mbase = m0 + wm * 64 + (lane >> 2);
    const int nbase = n0 + wn * 32 + 2 * (lane & 3);
    if (MODE == 0) {
        __nv_bfloat16* Hp = (z == 0) ? Qh : (z == 1) ? Kh : Vh;
        __nv_bfloat16* Lp = (z == 0) ? Ql : (z == 1) ? Kl : Vl;
        const float sc = (z == 0) ? 0.125f : 1.0f;
        #pragma unroll
        for (int mt = 0; mt < 4; mt++) {
            #pragma unroll
            for (int nt = 0; nt < 4; nt++) {
                int m = mbase + mt * 16;
                int n = nbase + nt * 8;
                int h = n >> 6, d0 = n & 63;
                int b = m >> 11;
                size_t base = (((size_t)(b * H_ + h)) * S_ + (m & 2047)) * D_ + d0;
                #pragma unroll
                for (int half = 0; half < 2; half++) {
                    float v0 = acc[mt][nt][2 * half] * sc;
                    float v1 = acc[mt][nt][2 * half + 1] * sc;
                    __nv_bfloat16 h0, l0, h1, l1;
                    split1(v0, h0, l0);
                    split1(v1, h1, l1);
                    __nv_bfloat162 hv; hv.x = h0; hv.y = h1;
                    __nv_bfloat162 lv; lv.x = l0; lv.y = l1;
                    size_t a = base + (size_t)half * 8 * D_;
                    *(__nv_bfloat162*)(Hp + a) = hv;
                    *(__nv_bfloat162*)(Lp + a) = lv;
                }
            }
        }
    } else {
        #pragma unroll
        for (int mt = 0; mt < 4; mt++) {
            #pragma unroll
            for (int nt = 0; nt < 4; nt++) {
                int m = mbase + mt * 16;
                int n = nbase + nt * 8;
                size_t base = (size_t)m * E_ + n;
                *(float2*)(Of + base) = make_float2(acc[mt][nt][0], acc[mt][nt][1]);
                *(float2*)(Of + base + 8 * E_) = make_float2(acc[mt][nt][2], acc[mt][nt][3]);
            }
        }
    }
}

// ---------------- mma.sync flash attention (causal, bf16 split) ----------------
#define AROWB 144                    // 72 bf16 per padded row
#define SQL   (128 * AROWB)          // 18432
#define SKV0  (2 * 128 * AROWB)      // 36864
#define KVSTAGE (4 * 64 * AROWB)     // KH,KL,VH,VL = 36864
#define KARR  (64 * AROWB)           // 9216 per sub-array
#define ATT_SMEM (SKV0 + 2 * KVSTAGE)  // 110592

__global__ __launch_bounds__(256, 2) void flash_mma(
    const __nv_bfloat16* __restrict__ Qh, const __nv_bfloat16* __restrict__ Ql,
    const __nv_bfloat16* __restrict__ Kh, const __nv_bfloat16* __restrict__ Kl,
    const __nv_bfloat16* __restrict__ Vh, const __nv_bfloat16* __restrict__ Vl,
    __nv_bfloat16* __restrict__ Ohi, __nv_bfloat16* __restrict__ Olo)
{
    extern __shared__ char smem[];
    const unsigned sb = smem_u32(smem);
    const int tid = threadIdx.x;
    const int lane = tid & 31, wq = tid >> 5;
    const int bx = gridDim.x - 1 - blockIdx.x;   // heavy blocks first
    const int bh = blockIdx.y;
    const int q0 = bx * 128;
    const size_t hb = (size_t)bh * S_ * D_;

    // Q tiles (hi+lo), loaded once: 2048 x 16B
    #pragma unroll
    for (int j = 0; j < 8; j++) {
        int id = tid + j * 256;
        int arr = id >> 10;
        int r = (id & 1023) >> 3, c = id & 7;
        unsigned off = (arr ? SQL : 0) + r * AROWB + c * 16;
        const __nv_bfloat16* src = (arr ? Ql : Qh) + hb + (size_t)(q0 + r) * D_ + c * 8;
        cpasync16(sb + off, src);
    }
    auto load_kv = [&](int stage, int kv0) {
        unsigned base = sb + SKV0 + (unsigned)stage * KVSTAGE;
        #pragma unroll
        for (int j = 0; j < 8; j++) {
            int id = tid + j * 256;
            int arr = id >> 9;       // 0 KH, 1 KL, 2 VH, 3 VL
            int r = (id & 511) >> 3, c = id & 7;
            unsigned off = (unsigned)arr * KARR + r * AROWB + c * 16;
            const __nv_bfloat16* src =
                (arr == 0 ? Kh : arr == 1 ? Kl : arr == 2 ? Vh : Vl)
                + hb + (size_t)(kv0 + r) * D_ + c * 8;
            cpasync16(base + off, src);
        }
    };

    const int nt = 2 * bx + 2;
    load_kv(0, 0);
    CP_COMMIT;

    float sacc[8][4], oacc[8][4];
    float mrow[2] = {-1e30f, -1e30f}, lrow[2] = {0.f, 0.f};
    #pragma unroll
    for (int j = 0; j < 8; j++)
        #pragma unroll
        for (int c = 0; c < 4; c++) oacc[j][c] = 0.f;

    const unsigned qoff = sb + (unsigned)((wq * 16 + (lane & 15)) * AROWB + (lane >> 4) * 16);
    const unsigned krow = (unsigned)((lane & 7) + ((lane >> 4) << 3));
    const unsigned kcolb = (unsigned)(((lane >> 3) & 1) * 16);
    const unsigned vrow = (unsigned)((lane & 7) + (((lane >> 3) & 1) << 3));
    const unsigned vcolb = (unsigned)((lane >> 4) * 16);
    const int rl0 = wq * 16 + (lane >> 2);

    for (int t0 = 0; t0 < nt; t0++) {
        const int kv0 = t0 * 64;
        const unsigned kvb = sb + SKV0 + (unsigned)(t0 & 1) * KVSTAGE;
        CP_WAIT0;
        __syncthreads();

        // ---- S = Q K^T (3-product split, jj-pair interleaved) ----
        #pragma unroll
        for (int j = 0; j < 8; j++) {
            sacc[j][0] = 0.f; sacc[j][1] = 0.f; sacc[j][2] = 0.f; sacc[j][3] = 0.f;
        }
        #pragma unroll
        for (int ks = 0; ks < 4; ks++) {
            unsigned qh4[4], ql4[4];
            ldm_x4(qh4, qoff + ks * 32);
            ldm_x4(ql4, qoff + SQL + ks * 32);
            #pragma unroll
            for (int p = 0; p < 2; p++) {           // jj pairs (2p, 2p+1)
                unsigned b0h[4], b0l[4], b1h[4], b1l[4];
                unsigned ko0 = kvb + ((2 * p)     * 16 + krow) * AROWB + kcolb + ks * 32;
                unsigned ko1 = kvb + ((2 * p + 1) * 16 + krow) * AROWB + kcolb + ks * 32;
                ldm_x4(b0h, ko0);
                ldm_x4(b0l, ko0 + KARR);
                ldm_x4(b1h, ko1);
                ldm_x4(b1l, ko1 + KARR);
                float* a0 = sacc[4 * p + 0];
                float* a1 = sacc[4 * p + 1];
                float* a2 = sacc[4 * p + 2];
                float* a3 = sacc[4 * p + 3];
                mma_bf16(a0, qh4, b0h);     mma_bf16(a1, qh4, b0h + 2);
                mma_bf16(a2, qh4, b1h);     mma_bf16(a3, qh4, b1h + 2);
                mma_bf16(a0, qh4, b0l);     mma_bf16(a1, qh4, b0l + 2);
                mma_bf16(a2, qh4, b1l);     mma_bf16(a3, qh4, b1l + 2);
                mma_bf16(a0, ql4, b0h);     mma_bf16(a1, ql4, b0h + 2);
                mma_bf16(a2, ql4, b1h);     mma_bf16(a3, ql4, b1h + 2);
            }
        }

        // issue next tile's KV loads now — overlaps softmax + PV below
        if (t0 + 1 < nt) {
            load_kv((t0 + 1) & 1, kv0 + 64);
            CP_COMMIT;
        }

        // ---- mask + online softmax (fp32, poly exp) ----
        const bool maskt = (t0 >= nt - 2);
        const int rel = kv0 - q0;
        #pragma unroll
        for (int h = 0; h < 2; h++) {
            const int rloc = rl0 + 8 * h;
            if (maskt) {
                #pragma unroll
                for (int j = 0; j < 8; j++) {
                    int c0 = 8 * j + 2 * (lane & 3) + rel;
                    if (c0 > rloc)     sacc[j][2 * h]     = -1e30f;
                    if (c0 + 1 > rloc) sacc[j][2 * h + 1] = -1e30f;
                }
            }
            float mx = mrow[h];
            #pragma unroll
            for (int j = 0; j < 8; j++)
                mx = fmaxf(mx, fmaxf(sacc[j][2 * h], sacc[j][2 * h + 1]));
            mx = fmaxf(mx, __shfl_xor_sync(0xffffffffu, mx, 1));
            mx = fmaxf(mx, __shfl_xor_sync(0xffffffffu, mx, 2));
            float alpha = fexp(mrow[h] - mx);
            mrow[h] = mx;
            float rs = 0.f;
            #pragma unroll
            for (int j = 0; j < 8; j++) {
                float p0 = fexp(sacc[j][2 * h] - mx);
                float p1 = fexp(sacc[j][2 * h + 1] - mx);
                sacc[j][2 * h] = p0; sacc[j][2 * h + 1] = p1;
                rs += p0 + p1;
            }
            rs += __shfl_xor_sync(0xffffffffu, rs, 1);
            rs += __shfl_xor_sync(0xffffffffu, rs, 2);
            lrow[h] = lrow[h] * alpha + rs;
            #pragma unroll
            for (int j = 0; j < 8; j++) {
                oacc[j][2 * h] *= alpha;
                oacc[j][2 * h + 1] *= alpha;
            }
        }

        // ---- O += P V (P in registers, g-pair interleaved) ----
        #pragma unroll
        for (int ks = 0; ks < 4; ks++) {
            unsigned phi[4], plo[4];
            #pragma unroll
            for (int i = 0; i < 4; i++) {
                int j = 2 * ks + (i >> 1);
                int bse = (i & 1) * 2;
                float p0 = sacc[j][bse], p1 = sacc[j][bse + 1];
                unsigned hp = pack_bf2(p0, p1);
                float2 hf = unpack_bf2(hp);
                phi[i] = hp;
                plo[i] = pack_bf2(p0 - hf.x, p1 - hf.y);
            }
            #pragma unroll
            for (int gp = 0; gp < 2; gp++) {        // g pairs (2gp, 2gp+1)
                unsigned vah[4], val[4], vbh2[4], vbl2[4];
                unsigned vo0 = kvb + 2 * KARR + (ks * 16 + vrow) * AROWB + vcolb + (2 * gp) * 32;
                unsigned vo1 = vo0 + 32;
                ldm_x4_t(vah, vo0);
                ldm_x4_t(val, vo0 + KARR);
                ldm_x4_t(vbh2, vo1);
                ldm_x4_t(vbl2, vo1 + KARR);
                float* o0 = oacc[4 * gp + 0];
                float* o1 = oacc[4 * gp + 1];
                float* o2 = oacc[4 * gp + 2];
                float* o3 = oacc[4 * gp + 3];
                mma_bf16(o0, phi, vah);     mma_bf16(o1, phi, vah + 2);
                mma_bf16(o2, phi, vbh2);    mma_bf16(o3, phi, vbh2 + 2);
                mma_bf16(o0, phi, val);     mma_bf16(o1, phi, val + 2);
                mma_bf16(o2, phi, vbl2);    mma_bf16(o3, phi, vbl2 + 2);
                mma_bf16(o0, plo, vah);     mma_bf16(o1, plo, vah + 2);
                mma_bf16(o2, plo, vbh2);    mma_bf16(o3, plo, vbh2 + 2);
            }
        }
    }

    // ---- epilogue: O/l -> bf16 hi/lo, row-major (b*S+s, h*64+d) ----
    const int b = bh >> 4, hd = bh & 15;
    #pragma unroll
    for (int hh = 0; hh < 2; hh++) {
        float linv = 1.f / lrow[hh];
        int s = q0 + wq * 16 + (lane >> 2) + 8 * hh;
        size_t rowb = ((size_t)b * S_ + s) * E_ + hd * D_ + 2 * (lane & 3);
        #pragma unroll
        for (int j = 0; j < 8; j++) {
            float o0 = oacc[j][2 * hh] * linv;
            float o1 = oacc[j][2 * hh + 1] * linv;
            __nv_bfloat16 h0, l0, h1, l1;
            split1(o0, h0, l0);
            split1(o1, h1, l1);
            __nv_bfloat162 hv; hv.x = h0; hv.y = h1;
            __nv_bfloat162 lv; lv.x = l0; lv.y = l1;
            *(__nv_bfloat162*)(Ohi + rowb + 8 * j) = hv;
            *(__nv_bfloat162*)(Olo + rowb + 8 * j) = lv;
        }
    }
}

// ---------------- mod = silu(cond) @ Wc^T + bc ----------------
__global__ __launch_bounds__(256) void mod_kernel(
    const float* __restrict__ cond, const float* __restrict__ Wc,
    const float* __restrict__ bc, float* __restrict__ mod)
{
    __shared__ float sc[C_];
    int gid = blockIdx.x * 256 + threadIdx.x;
    int b = gid >> 11;
    int j = gid & 2047;
    {
        float c = cond[b * C_ + threadIdx.x];
        sc[threadIdx.x] = c / (1.f + __expf(-c));
    }
    __syncthreads();
    const float* wr = Wc + (size_t)j * C_;
    float acc = 0.f;
    #pragma unroll 8
    for (int c = 0; c < C_; c += 4) {
        float4 w = *(const float4*)&wr[c];
        acc += sc[c] * w.x + sc[c + 1] * w.y + sc[c + 2] * w.z + sc[c + 3] * w.w;
    }
    mod[gid] = acc + bc[j];
}

// ---------------- RMSNorm + FiLM ----------------
__global__ __launch_bounds__(256) void norm_film(
    const float* __restrict__ X, const float* __restrict__ gscale,
    const float* __restrict__ mod, float* __restrict__ out)
{
    const int m = blockIdx.x;
    const int b = m >> 11;
    const float* xr = X + (size_t)m * E_;
    const int e = threadIdx.x * 4;
    float4 v = *(const float4*)&xr[e];
    float ss = v.x * v.x + v.y * v.y + v.z * v.z + v.w * v.w;
    #pragma unroll
    for (int off = 16; off; off >>= 1)
        ss += __shfl_xor_sync(0xffffffffu, ss, off);
    __shared__ float red[8];
    if ((threadIdx.x & 31) == 0) red[threadIdx.x >> 5] = ss;
    __syncthreads();
    float tot = 0.f;
    #pragma unroll
    for (int i = 0; i < 8; i++) tot += red[i];
    float inv = rsqrtf(tot * (1.f / (float)E_) + 1e-6f);

    const float* mb = mod + (size_t)b * 2 * E_;
    float4 g  = *(const float4*)&gscale[e];
    float4 sh = *(const float4*)&mb[e];
    float4 sv = *(const float4*)&mb[E_ + e];
    float4 o;
    o.x = v.x * inv * g.x * (1.f + sv.x) + sh.x;
    o.y = v.y * inv * g.y * (1.f + sv.y) + sh.y;
    o.z = v.z * inv * g.z * (1.f + sv.z) + sh.z;
    o.w = v.w * inv * g.w * (1.f + sv.w) + sh.w;
    *(float4*)&out[(size_t)m * E_ + e] = o;
}

// ---------------- launch ----------------
extern "C" void kernel_launch(void* const* d_in, const int* in_sizes, int n_in,
                              void* d_out, int out_size)
{
    const float* x    = (const float*)d_in[0];
    // d_in[1] = mask: provably triu(ones,k=1) causal -> applied analytically
    const float* cond = (const float*)d_in[2];
    const float* Wq   = (const float*)d_in[3];
    const float* Wk   = (const float*)d_in[4];
    const float* Wv   = (const float*)d_in[5];
    const float* Wo   = (const float*)d_in[6];
    const float* rsc  = (const float*)d_in[7];
    const float* Wc   = (const float*)d_in[8];
    const float* bc   = (const float*)d_in[9];
    float* out = (float*)d_out;

    float *proj, *mod;
    __nv_bfloat16 *xhi, *xlo, *whi, *wlo, *ahi, *alo;
    __nv_bfloat16 *qh, *ql, *kh, *kl, *vh, *vl;
    cudaGetSymbolAddress((void**)&proj, g_proj);
    cudaGetSymbolAddress((void**)&mod,  g_mod);
    cudaGetSymbolAddress((void**)&xhi,  g_xhi);
    cudaGetSymbolAddress((void**)&xlo,  g_xlo);
    cudaGetSymbolAddress((void**)&whi,  g_whi);
    cudaGetSymbolAddress((void**)&wlo,  g_wlo);
    cudaGetSymbolAddress((void**)&ahi,  g_ahi);
    cudaGetSymbolAddress((void**)&alo,  g_alo);
    cudaGetSymbolAddress((void**)&qh,   g_qh);
    cudaGetSymbolAddress((void**)&ql,   g_ql);
    cudaGetSymbolAddress((void**)&kh,   g_kh);
    cudaGetSymbolAddress((void**)&kl,   g_kl);
    cudaGetSymbolAddress((void**)&vh,   g_vh);
    cudaGetSymbolAddress((void**)&vl,   g_vl);

    cudaFuncSetAttribute(gemm_mma<0>, cudaFuncAttributeMaxDynamicSharedMemorySize, GSM);
    cudaFuncSetAttribute(gemm_mma<1>, cudaFuncAttributeMaxDynamicSharedMemorySize, GSM);
    cudaFuncSetAttribute(flash_mma, cudaFuncAttributeMaxDynamicSharedMemorySize, ATT_SMEM);

    // fp32 -> bf16 hi/lo splits
    conv_split<<<M_TOT * E_ / 1024, 256>>>(x, xhi, xlo);
    conv_split_w<<<dim3(E_ * E_ / 1024, 1, 4), 256>>>(Wq, Wk, Wv, Wo, whi, wlo);
    // conditioning modulation (independent)
    mod_kernel<<<(B_ * 2 * E_) / 256, 256>>>(cond, Wc, bc, mod);
    // QKV projections -> bf16 hi/lo (B,H,S,D); q pre-scaled
    gemm_mma<0><<<dim3(E_ / BN, M_TOT / BM, 3), 256, GSM>>>(
        xhi, xlo, whi, wlo, qh, ql, kh, kl, vh, vl, nullptr);
    // causal flash attention on tensor cores -> bf16 hi/lo (m, E)
    flash_mma<<<dim3(S_ / 128, B_ * H_), 256, ATT_SMEM>>>(
        qh, ql, kh, kl, vh, vl, ahi, alo);
    // output projection -> fp32
    gemm_mma<1><<<dim3(E_ / BN, M_TOT / BM, 1), 256, GSM>>>(
        ahi, alo, whi, wlo, nullptr, nullptr, nullptr, nullptr, nullptr, nullptr, proj);
    // RMSNorm + FiLM
    norm_film<<<M_TOT, 256>>>(proj, rsc, mod, out);
}